// round 13
// baseline (speedup 1.0000x reference)
#include <cuda_runtime.h>
#include <cuda_bf16.h>
#include <math.h>
#include <stdint.h>

#define B_        32
#define N_NODE    200
#define N_REL     34
#define C_DIM     200
#define C_IN      1024
#define SENT_DIM  1024
#define FC_DIM    512
#define NBR_      (B_ * N_REL)            /* 1088 */
#define NN        (N_NODE * N_NODE)       /* 40000 */
#define RC        (N_REL * C_DIM)         /* 6800 */
#define ROWS      (B_ * N_NODE)           /* 6400 */
#define KP        224                     /* padded K for layer/kv tensor path */
#define WT_L      (KP * RC)               /* bf16 elems of layer W per layer */

// -------- device scratch (no allocations allowed) --------
__device__ float   g_x  [ROWS * C_DIM];
__device__ float   g_x2 [ROWS * C_DIM];
__device__ float   g_y  [(size_t)ROWS * RC];    // 174 MB
__device__ uint8_t g_nbr[(size_t)NBR_ * N_NODE * N_NODE];
__device__ int     g_cnt[NBR_ * N_NODE];
__device__ float   g_kv [ROWS * 400];           // fused k|v
__device__ float   g_q  [B_ * C_DIM];
__device__ float   g_gv [B_ * C_DIM];
// tensor-core operands (split bf16)
__device__ __nv_bfloat16 g_xhi[ROWS * KP];
__device__ __nv_bfloat16 g_xlo[ROWS * KP];
__device__ __nv_bfloat16 g_whi[3 * WT_L];
__device__ __nv_bfloat16 g_wlo[3 * WT_L];
__device__ __nv_bfloat16 g_ehi[ROWS * C_IN];    // gathered emb rows, split
__device__ __nv_bfloat16 g_elo[ROWS * C_IN];
__device__ __nv_bfloat16 g_cwhi[C_IN * C_DIM];  // cptW split
__device__ __nv_bfloat16 g_cwlo[C_IN * C_DIM];
__device__ __nv_bfloat16 g_wkvhi[KP * 400];     // [wk|wv] split, K padded
__device__ __nv_bfloat16 g_wkvlo[KP * 400];
__device__ float   g_bkv[400];

__device__ __forceinline__ float gelu_f(float x) {
    return 0.5f * x * (1.0f + erff(x * 0.70710678118654752f));
}

__device__ __forceinline__ uint32_t smem_u32(const void* p) {
    uint32_t a;
    asm("{ .reg .u64 t; cvta.to.shared.u64 t, %1; cvt.u32.u64 %0, t; }" : "=r"(a) : "l"(p));
    return a;
}
__device__ __forceinline__ void ldsm4(uint32_t* r, uint32_t addr) {
    asm volatile("ldmatrix.sync.aligned.m8n8.x4.shared.b16 {%0,%1,%2,%3}, [%4];"
                 : "=r"(r[0]), "=r"(r[1]), "=r"(r[2]), "=r"(r[3]) : "r"(addr));
}
__device__ __forceinline__ void ldsm4t(uint32_t* r, uint32_t addr) {
    asm volatile("ldmatrix.sync.aligned.m8n8.x4.trans.shared.b16 {%0,%1,%2,%3}, [%4];"
                 : "=r"(r[0]), "=r"(r[1]), "=r"(r[2]), "=r"(r[3]) : "r"(addr));
}
__device__ __forceinline__ void mma16816(float* c, const uint32_t* a, const uint32_t* b) {
    asm volatile(
        "mma.sync.aligned.m16n8k16.row.col.f32.bf16.bf16.f32 "
        "{%0,%1,%2,%3}, {%4,%5,%6,%7}, {%8,%9}, {%0,%1,%2,%3};"
        : "+f"(c[0]), "+f"(c[1]), "+f"(c[2]), "+f"(c[3])
        : "r"(a[0]), "r"(a[1]), "r"(a[2]), "r"(a[3]), "r"(b[0]), "r"(b[1]));
}

// ---------------------------------------------------------------------------
// Build in-edge lists.
// ---------------------------------------------------------------------------
__global__ void k_build(const float* __restrict__ adj, uint8_t* __restrict__ nbr,
                        int* __restrict__ cnt) {
    int br = blockIdx.x;
    int i = threadIdx.x;
    if (i < N_NODE) {
        const float* a = adj + (size_t)br * NN + i;
        uint8_t* nb = nbr + ((size_t)br * N_NODE + i) * N_NODE;
        int c = 0;
        for (int j = 0; j < N_NODE; j++)
            if (a[(size_t)j * N_NODE] != 0.f) nb[c++] = (uint8_t)j;
        cnt[br * N_NODE + i] = c;
    }
}

// ---------------------------------------------------------------------------
// Fused permute + split + K-pad of gnn_w:
// whi/wlo[l][k][r*200+o] = split(gw[l][k][o*34+r]);  rows k>=200 are zero.
// One block per (l, k) with k in 0..KP-1 (672 blocks).
// ---------------------------------------------------------------------------
__global__ void k_wprep(const float* __restrict__ gw,
                        __nv_bfloat16* __restrict__ hi, __nv_bfloat16* __restrict__ lo) {
    __shared__ float s[RC];
    int bid = blockIdx.x;
    int l = bid / KP, k = bid % KP;
    size_t dst = ((size_t)l * KP + k) * RC;
    if (k < C_DIM) {
        const float* src = gw + ((size_t)l * C_DIM + k) * RC;
        for (int i = threadIdx.x; i < RC; i += 256) s[i] = src[i];
        __syncthreads();
        for (int n = threadIdx.x; n < RC; n += 256) {
            int r = n / C_DIM, o = n % C_DIM;
            float v = s[o * N_REL + r];
            __nv_bfloat16 h = __float2bfloat16(v);
            hi[dst + n] = h;
            lo[dst + n] = __float2bfloat16(v - __bfloat162float(h));
        }
    } else {
        __nv_bfloat16 z = __float2bfloat16(0.f);
        for (int n = threadIdx.x; n < RC; n += 256) { hi[dst + n] = z; lo[dst + n] = z; }
    }
}

// ---------------------------------------------------------------------------
// Split cptW fp32 [1024][200] -> bf16 hi/lo (no padding; K=1024 = 32*32).
// ---------------------------------------------------------------------------
__global__ void k_cwsplit(const float* __restrict__ w,
                          __nv_bfloat16* __restrict__ hi, __nv_bfloat16* __restrict__ lo) {
    int idx = blockIdx.x * 256 + threadIdx.x;
    if (idx >= C_IN * C_DIM) return;
    float v = w[idx];
    __nv_bfloat16 h = __float2bfloat16(v);
    hi[idx] = h;
    lo[idx] = __float2bfloat16(v - __bfloat162float(h));
}

// ---------------------------------------------------------------------------
// Build [wk|wv] split bf16 [224][400]; bias concat.
// ---------------------------------------------------------------------------
__global__ void k_wkvsplit(const float* __restrict__ wk, const float* __restrict__ wv,
                           const float* __restrict__ bk, const float* __restrict__ bv,
                           __nv_bfloat16* __restrict__ hi, __nv_bfloat16* __restrict__ lo,
                           float* __restrict__ bkv) {
    int idx = blockIdx.x * 256 + threadIdx.x;
    if (idx < 400) bkv[idx] = (idx < C_DIM) ? bk[idx] : bv[idx - C_DIM];
    if (idx >= KP * 400) return;
    int k = idx / 400, n = idx % 400;
    float v = 0.f;
    if (k < C_DIM) v = (n < C_DIM) ? wk[k * C_DIM + n] : wv[k * C_DIM + (n - C_DIM)];
    __nv_bfloat16 h = __float2bfloat16(v);
    hi[idx] = h;
    lo[idx] = __float2bfloat16(v - __bfloat162float(h));
}

// ---------------------------------------------------------------------------
// Gather + split emb rows: hi/lo [ROWS][1024] = split(emb[concepts[row]][k]).
// ---------------------------------------------------------------------------
__global__ void k_gsplit(const float* __restrict__ emb, const int* __restrict__ concepts,
                         __nv_bfloat16* __restrict__ hi, __nv_bfloat16* __restrict__ lo) {
    int idx = blockIdx.x * 256 + threadIdx.x;
    if (idx >= ROWS * C_IN) return;
    int row = idx >> 10, k = idx & 1023;
    float v = emb[(size_t)concepts[row] * C_IN + k];
    __nv_bfloat16 h = __float2bfloat16(v);
    hi[idx] = h;
    lo[idx] = __float2bfloat16(v - __bfloat162float(h));
}

// ---------------------------------------------------------------------------
// Zero the K-pad (cols 200..223) of xhi/xlo once; epilogues maintain it after.
// ---------------------------------------------------------------------------
__global__ void k_padzero(__nv_bfloat16* __restrict__ hi, __nv_bfloat16* __restrict__ lo) {
    int idx = blockIdx.x * 256 + threadIdx.x;
    if (idx >= ROWS * 24) return;
    int row = idx / 24, col = C_DIM + idx % 24;
    hi[(size_t)row * KP + col] = __float2bfloat16(0.f);
    lo[(size_t)row * KP + col] = __float2bfloat16(0.f);
}

// ---------------------------------------------------------------------------
// Generalized tensor-core GEMM (mma.sync bf16, split-precision 3-pass),
// DOUBLE-BUFFERED (2-stage SMEM, one __syncthreads per iteration):
// out[m][n] = act(sum_k A[m][k] * W[k][n] + bias)
// 128x128 CTA tile, 8 warps (2M x 4N), each warp 64x32 via m16n8k16.
// KCH = k32-chunks per pass. SPLITOUT: GELU + emit bf16 hi/lo (stride KP).
// ---------------------------------------------------------------------------
template <int KCH, bool BIAS, bool SPLITOUT>
__global__ void __launch_bounds__(256)
k_mma(const __nv_bfloat16* __restrict__ xhi, const __nv_bfloat16* __restrict__ xlo,
      const __nv_bfloat16* __restrict__ whi, const __nv_bfloat16* __restrict__ wlo,
      const float* __restrict__ bias, float* __restrict__ out, int ldc, int N,
      __nv_bfloat16* __restrict__ ohi, __nv_bfloat16* __restrict__ olo) {
    const int KPA = KCH * 32;
    __shared__ __align__(16) __nv_bfloat16 sA[2][128][40];    // 2 stages, +8 pad
    __shared__ __align__(16) __nv_bfloat16 sB[2][32][136];
    const uint32_t SA_ST = 128 * 40 * 2;   // bytes per A stage
    const uint32_t SB_ST = 32 * 136 * 2;   // bytes per B stage
    const int t = threadIdx.x;
    const int lane = t & 31, wid = t >> 5;
    const int wm = (wid & 1) * 64, wn = (wid >> 1) * 32;
    const int m0 = blockIdx.y * 128, n0 = blockIdx.x * 128;

    // global loader coords
    const int arow = t >> 1, acol = (t & 1) * 16;    // A: 2 x 16B per thread
    const int brow = t >> 3, bcol = (t & 7) * 16;    // B: 2 x 16B per thread
    const bool bg0 = (n0 + bcol) < N;
    const bool bg1 = (n0 + bcol + 8) < N;

    // ldmatrix smem addresses (bytes, stage 0)
    const uint32_t sa_b = smem_u32(&sA[0][0][0]);
    const uint32_t sb_b = smem_u32(&sB[0][0][0]);
    uint32_t saAddr[4], sbAddr[2];
    #pragma unroll
    for (int mi = 0; mi < 4; mi++)
        saAddr[mi] = sa_b + ((wm + mi * 16 + (lane & 15)) * 40 + (lane >> 4) * 8) * 2;
    #pragma unroll
    for (int nb = 0; nb < 2; nb++)
        sbAddr[nb] = sb_b + ((lane & 15) * 136 + wn + nb * 16 + (lane >> 4) * 8) * 2;

    float acc[4][4][4];
    #pragma unroll
    for (int i = 0; i < 4; i++)
        #pragma unroll
        for (int j = 0; j < 4; j++)
            #pragma unroll
            for (int q = 0; q < 4; q++) acc[i][j][q] = 0.f;

    const uint4 z4 = make_uint4(0, 0, 0, 0);
    uint4 aP0, aP1, bP0, bP1;

    // prefetch chunk 0 and store into stage 0
    {
        const __nv_bfloat16* ar = xhi + (size_t)(m0 + arow) * KPA + acol;
        aP0 = *reinterpret_cast<const uint4*>(ar);
        aP1 = *reinterpret_cast<const uint4*>(ar + 8);
        const __nv_bfloat16* br = whi + (size_t)brow * N + n0 + bcol;
        bP0 = bg0 ? *reinterpret_cast<const uint4*>(br) : z4;
        bP1 = bg1 ? *reinterpret_cast<const uint4*>(br + 8) : z4;
        *reinterpret_cast<uint4*>(&sA[0][arow][acol])     = aP0;
        *reinterpret_cast<uint4*>(&sA[0][arow][acol + 8]) = aP1;
        *reinterpret_cast<uint4*>(&sB[0][brow][bcol])     = bP0;
        *reinterpret_cast<uint4*>(&sB[0][brow][bcol + 8]) = bP1;
    }

    const int NITER = 3 * KCH;
    for (int it = 0; it < NITER; it++) {
        const int cur = it & 1, nxt = cur ^ 1;
        __syncthreads();   // stage cur stores visible; stage nxt free (compute it-1 done)

        // prefetch chunk it+1 into regs (lands during compute)
        if (it + 1 < NITER) {
            int p = (it + 1) / KCH, kc = ((it + 1) % KCH) * 32;
            const __nv_bfloat16* Ap = (p < 2) ? xhi : xlo;
            const __nv_bfloat16* Bp = (p == 1) ? wlo : whi;
            const __nv_bfloat16* ar = Ap + (size_t)(m0 + arow) * KPA + kc + acol;
            aP0 = *reinterpret_cast<const uint4*>(ar);
            aP1 = *reinterpret_cast<const uint4*>(ar + 8);
            const __nv_bfloat16* br = Bp + (size_t)(kc + brow) * N + n0 + bcol;
            bP0 = bg0 ? *reinterpret_cast<const uint4*>(br) : z4;
            bP1 = bg1 ? *reinterpret_cast<const uint4*>(br + 8) : z4;
        }

        // compute on stage cur
        const uint32_t saOff = cur * SA_ST, sbOff = cur * SB_ST;
        #pragma unroll
        for (int ks = 0; ks < 2; ks++) {
            uint32_t bf[8];
            ldsm4t(bf,     sbAddr[0] + sbOff + ks * 4352);   // 16 rows * 272B
            ldsm4t(bf + 4, sbAddr[1] + sbOff + ks * 4352);
            uint32_t af[4][4];
            #pragma unroll
            for (int mi = 0; mi < 4; mi++)
                ldsm4(af[mi], saAddr[mi] + saOff + ks * 32);
            #pragma unroll
            for (int mi = 0; mi < 4; mi++) {
                mma16816(acc[mi][0], af[mi], bf + 0);
                mma16816(acc[mi][1], af[mi], bf + 2);
                mma16816(acc[mi][2], af[mi], bf + 4);
                mma16816(acc[mi][3], af[mi], bf + 6);
            }
        }

        // store prefetched chunk into stage nxt (overlaps compute; safe: readers
        // of nxt finished at compute(it-1), ordered by the sync above)
        if (it + 1 < NITER) {
            *reinterpret_cast<uint4*>(&sA[nxt][arow][acol])     = aP0;
            *reinterpret_cast<uint4*>(&sA[nxt][arow][acol + 8]) = aP1;
            *reinterpret_cast<uint4*>(&sB[nxt][brow][bcol])     = bP0;
            *reinterpret_cast<uint4*>(&sB[nxt][brow][bcol + 8]) = bP1;
        }
    }

    // epilogue: c-frag rows = lane>>2 (+8), cols = (lane&3)*2 (+1)
    #pragma unroll
    for (int mi = 0; mi < 4; mi++) {
        int r = m0 + wm + mi * 16 + (lane >> 2);
        #pragma unroll
        for (int nj = 0; nj < 4; nj++) {
            int c = n0 + wn + nj * 8 + (lane & 3) * 2;
            if (c < N) {
                #pragma unroll
                for (int half = 0; half < 2; half++) {
                    int rr = r + half * 8;
                    float v0 = acc[mi][nj][half * 2 + 0];
                    float v1 = acc[mi][nj][half * 2 + 1];
                    if (BIAS) { v0 += bias[c]; v1 += bias[c + 1]; }
                    if (SPLITOUT) {
                        v0 = gelu_f(v0); v1 = gelu_f(v1);
                        __align__(4) __nv_bfloat16 h2[2], l2[2];
                        h2[0] = __float2bfloat16(v0);
                        h2[1] = __float2bfloat16(v1);
                        l2[0] = __float2bfloat16(v0 - __bfloat162float(h2[0]));
                        l2[1] = __float2bfloat16(v1 - __bfloat162float(h2[1]));
                        *reinterpret_cast<uint32_t*>(&ohi[(size_t)rr * KP + c]) =
                            *reinterpret_cast<const uint32_t*>(h2);
                        *reinterpret_cast<uint32_t*>(&olo[(size_t)rr * KP + c]) =
                            *reinterpret_cast<const uint32_t*>(l2);
                    }
                    *reinterpret_cast<float2*>(&out[(size_t)rr * ldc + c]) =
                        make_float2(v0, v1);
                }
            }
        }
    }
}

// ---------------------------------------------------------------------------
// fp32 tiled GEMM (q only): 128x128x16, 8x8 microtiles, conflict-free.
// ---------------------------------------------------------------------------
template <bool GELU, bool BIAS>
__global__ void __launch_bounds__(256, 2)
k_gemm(const float* __restrict__ A, const int* __restrict__ gather, int lda,
       const float* __restrict__ Bm, int ldb, const float* __restrict__ bias,
       float* __restrict__ C, int ldc, int M, int N, int K) {
    __shared__ __align__(16) float sA[16][132];
    __shared__ __align__(16) float sB[16][128];
    const int t = threadIdx.x;
    const int n0 = blockIdx.x * 128, m0 = blockIdx.y * 128;
    const int rowA = t >> 1, kqA = (t & 1) * 8;
    const int kkB = t >> 4, nqB = (t & 15) * 4;
    const int tr4 = (t >> 4) * 4, tc4 = (t & 15) * 4;

    const int gm = m0 + rowA;
    const float* arow = nullptr;
    if (gm < M) arow = A + (size_t)(gather ? gather[gm] : gm) * lda;
    const bool bn0 = (n0 + nqB) < N;
    const bool bn1 = (n0 + 64 + nqB) < N;

    const float4 z4 = make_float4(0.f, 0.f, 0.f, 0.f);
    float4 aR0 = z4, aR1 = z4, bR0 = z4, bR1 = z4;
    {
        int ka = kqA;
        if (arow && ka < K) {
            aR0 = *reinterpret_cast<const float4*>(arow + ka);
            aR1 = *reinterpret_cast<const float4*>(arow + ka + 4);
        }
        int kb = kkB;
        if (kb < K) {
            const float* bp = Bm + (size_t)kb * ldb + n0 + nqB;
            if (bn0) bR0 = *reinterpret_cast<const float4*>(bp);
            if (bn1) bR1 = *reinterpret_cast<const float4*>(bp + 64);
        }
    }

    float acc[8][8] = {};
    for (int k0 = 0; k0 < K; k0 += 16) {
        __syncthreads();
        sA[kqA + 0][rowA] = aR0.x; sA[kqA + 1][rowA] = aR0.y;
        sA[kqA + 2][rowA] = aR0.z; sA[kqA + 3][rowA] = aR0.w;
        sA[kqA + 4][rowA] = aR1.x; sA[kqA + 5][rowA] = aR1.y;
        sA[kqA + 6][rowA] = aR1.z; sA[kqA + 7][rowA] = aR1.w;
        *reinterpret_cast<float4*>(&sB[kkB][nqB])      = bR0;
        *reinterpret_cast<float4*>(&sB[kkB][64 + nqB]) = bR1;

        int k1 = k0 + 16;
        if (k1 < K) {
            aR0 = z4; aR1 = z4; bR0 = z4; bR1 = z4;
            int ka = k1 + kqA;
            if (arow && ka < K) {
                aR0 = *reinterpret_cast<const float4*>(arow + ka);
                aR1 = *reinterpret_cast<const float4*>(arow + ka + 4);
            }
            int kb = k1 + kkB;
            if (kb < K) {
                const float* bp = Bm + (size_t)kb * ldb + n0 + nqB;
                if (bn0) bR0 = *reinterpret_cast<const float4*>(bp);
                if (bn1) bR1 = *reinterpret_cast<const float4*>(bp + 64);
            }
        }
        __syncthreads();

        #pragma unroll
        for (int kk = 0; kk < 16; kk++) {
            float4 a0 = *reinterpret_cast<const float4*>(&sA[kk][tr4]);
            float4 a1 = *reinterpret_cast<const float4*>(&sA[kk][64 + tr4]);
            float4 b0 = *reinterpret_cast<const float4*>(&sB[kk][tc4]);
            float4 b1 = *reinterpret_cast<const float4*>(&sB[kk][64 + tc4]);
            const float av[8] = {a0.x, a0.y, a0.z, a0.w, a1.x, a1.y, a1.z, a1.w};
            const float bv[8] = {b0.x, b0.y, b0.z, b0.w, b1.x, b1.y, b1.z, b1.w};
            #pragma unroll
            for (int i = 0; i < 8; i++)
                #pragma unroll
                for (int j = 0; j < 8; j++)
                    acc[i][j] += av[i] * bv[j];
        }
    }

    #pragma unroll
    for (int i = 0; i < 8; i++) {
        int m = m0 + ((i < 4) ? (tr4 + i) : (64 + tr4 + i - 4));
        if (m >= M) continue;
        #pragma unroll
        for (int jh = 0; jh < 2; jh++) {
            int n = n0 + jh * 64 + tc4;
            if (n >= N) continue;
            float4 v;
            v.x = acc[i][jh * 4 + 0]; v.y = acc[i][jh * 4 + 1];
            v.z = acc[i][jh * 4 + 2]; v.w = acc[i][jh * 4 + 3];
            if (BIAS) {
                v.x += bias[n + 0]; v.y += bias[n + 1];
                v.z += bias[n + 2]; v.w += bias[n + 3];
            }
            if (GELU) {
                v.x = gelu_f(v.x); v.y = gelu_f(v.y);
                v.z = gelu_f(v.z); v.w = gelu_f(v.w);
            }
            *reinterpret_cast<float4*>(&C[(size_t)m * ldc + n]) = v;
        }
    }
}

// ---------------------------------------------------------------------------
// Sparse aggregate + GELU, fused with bf16 hi/lo split for the next layer.
// ---------------------------------------------------------------------------
__global__ void k_sagg(const float* __restrict__ y, const uint8_t* __restrict__ nbr,
                       const int* __restrict__ cnt, float* __restrict__ xout,
                       __nv_bfloat16* __restrict__ hi, __nv_bfloat16* __restrict__ lo) {
    int bi = blockIdx.x;
    int b = bi / N_NODE, i = bi % N_NODE;
    int t = threadIdx.x;                 // 64
    __shared__ uint8_t sj[N_NODE];
    float4 acc = make_float4(0.f, 0.f, 0.f, 0.f);
    const float* yb = y + (size_t)b * N_NODE * RC;
    for (int r = 0; r < N_REL; r++) {
        int br = b * N_REL + r;
        int c = cnt[br * N_NODE + i];
        const uint8_t* base = nbr + ((size_t)br * N_NODE + i) * N_NODE;
        for (int s = t; s < c; s += 64) sj[s] = base[s];
        __syncthreads();
        if (t < 50) {
            const float* yr = yb + r * C_DIM + t * 4;
            float4 tmp = make_float4(0.f, 0.f, 0.f, 0.f);
            #pragma unroll 4
            for (int s = 0; s < c; s++) {
                float4 v = *reinterpret_cast<const float4*>(yr + (size_t)sj[s] * RC);
                tmp.x += v.x; tmp.y += v.y; tmp.z += v.z; tmp.w += v.w;
            }
            float inv = 1.0f / (float)c;
            acc.x += tmp.x * inv; acc.y += tmp.y * inv;
            acc.z += tmp.z * inv; acc.w += tmp.w * inv;
        }
        __syncthreads();
    }
    if (t < 50) {
        float o[4];
        o[0] = gelu_f(acc.x); o[1] = gelu_f(acc.y);
        o[2] = gelu_f(acc.z); o[3] = gelu_f(acc.w);
        *reinterpret_cast<float4*>(&xout[(size_t)bi * C_DIM + t * 4]) =
            make_float4(o[0], o[1], o[2], o[3]);
        __align__(8) __nv_bfloat16 h4[4], l4[4];
        #pragma unroll
        for (int j = 0; j < 4; j++) {
            __nv_bfloat16 h = __float2bfloat16(o[j]);
            h4[j] = h;
            l4[j] = __float2bfloat16(o[j] - __bfloat162float(h));
        }
        *reinterpret_cast<uint2*>(&hi[(size_t)bi * KP + t * 4]) = *reinterpret_cast<const uint2*>(h4);
        *reinterpret_cast<uint2*>(&lo[(size_t)bi * KP + t * 4]) = *reinterpret_cast<const uint2*>(l4);
    } else if (t < 56) {
        int col = C_DIM + (t - 50) * 4;   // 200..220, zero the K pad
        uint2 z = make_uint2(0, 0);
        *reinterpret_cast<uint2*>(&hi[(size_t)bi * KP + col]) = z;
        *reinterpret_cast<uint2*>(&lo[(size_t)bi * KP + col]) = z;
    }
}

// ---------------------------------------------------------------------------
// Attention pooling; k/v fused in one buffer with row stride 400 (k@0, v@200).
// ---------------------------------------------------------------------------
__global__ void k_attn(const float* __restrict__ q, const float* __restrict__ kv,
                       const int* __restrict__ lens,
                       float* __restrict__ out, float* __restrict__ gv) {
    int b = blockIdx.x;
    int t = threadIdx.x;   // 256
    __shared__ float sq[C_DIM];
    __shared__ float sa[2][N_NODE];
    __shared__ float red[256];
    if (t < C_DIM) sq[t] = q[b * C_DIM + t];
    __syncthreads();
    int len = lens[b];
    for (int h = 0; h < 2; h++) {
        float s = -INFINITY;
        if (t < N_NODE && t < len) {
            float acc = 0.f;
            const float* kr = kv + ((size_t)(b * N_NODE + t)) * 400 + h * 100;
            #pragma unroll 4
            for (int d = 0; d < 100; d++) acc += sq[h * 100 + d] * kr[d];
            s = acc * 0.1f;
        }
        red[t] = s;
        __syncthreads();
        for (int off = 128; off > 0; off >>= 1) {
            if (t < off) red[t] = fmaxf(red[t], red[t + off]);
            __syncthreads();
        }
        float mx = red[0];
        __syncthreads();
        float e = (t < N_NODE && t < len) ? expf(s - mx) : 0.f;
        red[t] = e;
        __syncthreads();
        for (int off = 128; off > 0; off >>= 1) {
            if (t < off) red[t] += red[t + off];
            __syncthreads();
        }
        float inv = 1.f / red[0];
        __syncthreads();
        if (t < N_NODE) {
            float a = e * inv;
            sa[h][t] = a;
            out[32 + ((size_t)(h * B_ + b)) * N_NODE + t] = a;
        }
        __syncthreads();
    }
    if (t < C_DIM) {
        int h = t / 100, d = t % 100;
        float g = 0.f;
        for (int l = 0; l < N_NODE; l++)
            g += sa[h][l] * kv[((size_t)(b * N_NODE + l)) * 400 + 200 + h * 100 + d];
        gv[b * C_DIM + t] = g;
    }
}

// ---------------------------------------------------------------------------
// MLP readout.
// ---------------------------------------------------------------------------
__global__ void k_mlp(const float* __restrict__ gv, const float* __restrict__ sent,
                      const float* __restrict__ W0, const float* __restrict__ b0,
                      const float* __restrict__ lng, const float* __restrict__ lnb,
                      const float* __restrict__ W1, const float* __restrict__ b1,
                      float* __restrict__ out) {
    int b = blockIdx.x;
    int t = threadIdx.x;   // 512
    const int ZD = C_DIM + SENT_DIM;
    __shared__ float zz[C_DIM + SENT_DIM];
    __shared__ float red[512];
    for (int i = t; i < ZD; i += 512)
        zz[i] = (i < C_DIM) ? gv[b * C_DIM + i] : sent[(size_t)b * SENT_DIM + (i - C_DIM)];
    __syncthreads();
    float acc = b0[t];
    #pragma unroll 4
    for (int k = 0; k < ZD; k++) acc += zz[k] * W0[(size_t)k * FC_DIM + t];
    red[t] = acc; __syncthreads();
    for (int off = 256; off > 0; off >>= 1) { if (t < off) red[t] += red[t + off]; __syncthreads(); }
    float mu = red[0] * (1.f / FC_DIM);
    __syncthreads();
    float d = acc - mu;
    red[t] = d * d; __syncthreads();
    for (int off = 256; off > 0; off >>= 1) { if (t < off) red[t] += red[t + off]; __syncthreads(); }
    float var = red[0] * (1.f / FC_DIM);
    __syncthreads();
    float h1 = gelu_f(d * rsqrtf(var + 1e-5f) * lng[t] + lnb[t]);
    red[t] = h1 * W1[t]; __syncthreads();
    for (int off = 256; off > 0; off >>= 1) { if (t < off) red[t] += red[t + off]; __syncthreads(); }
    if (t == 0) out[b] = red[0] + b1[0];
}

// ---------------------------------------------------------------------------
extern "C" void kernel_launch(void* const* d_in, const int* in_sizes, int n_in,
                              void* d_out, int out_size) {
    const float* sent     = (const float*)d_in[0];
    const int*   concepts = (const int*)  d_in[1];
    const float* adj      = (const float*)d_in[2];
    const int*   lens     = (const int*)  d_in[3];
    const float* emb      = (const float*)d_in[4];
    const float* cptW     = (const float*)d_in[5];
    const float* cptb     = (const float*)d_in[6];
    const float* gnnw     = (const float*)d_in[7];
    const float* wq       = (const float*)d_in[8];
    const float* bq       = (const float*)d_in[9];
    const float* wk       = (const float*)d_in[10];
    const float* bk       = (const float*)d_in[11];
    const float* wv       = (const float*)d_in[12];
    const float* bv       = (const float*)d_in[13];
    const float* fcW0     = (const float*)d_in[14];
    const float* fcb0     = (const float*)d_in[15];
    const float* lng      = (const float*)d_in[16];
    const float* lnb      = (const float*)d_in[17];
    const float* fcW1     = (const float*)d_in[18];
    const float* fcb1     = (const float*)d_in[19];
    float* out = (float*)d_out;

    float *px, *px2, *py, *pkv, *pq, *pgv, *pbkv;
    __nv_bfloat16 *pxhi, *pxlo, *pwhi, *pwlo, *pehi, *pelo, *pcwhi, *pcwlo, *pwkvhi, *pwkvlo;
    uint8_t* pnbr; int* pcnt;
    cudaGetSymbolAddress((void**)&px,    g_x);
    cudaGetSymbolAddress((void**)&px2,   g_x2);
    cudaGetSymbolAddress((void**)&py,    g_y);
    cudaGetSymbolAddress((void**)&pnbr,  g_nbr);
    cudaGetSymbolAddress((void**)&pcnt,  g_cnt);
    cudaGetSymbolAddress((void**)&pkv,   g_kv);
    cudaGetSymbolAddress((void**)&pq,    g_q);
    cudaGetSymbolAddress((void**)&pgv,   g_gv);
    cudaGetSymbolAddress((void**)&pxhi,  g_xhi);
    cudaGetSymbolAddress((void**)&pxlo,  g_xlo);
    cudaGetSymbolAddress((void**)&pwhi,  g_whi);
    cudaGetSymbolAddress((void**)&pwlo,  g_wlo);
    cudaGetSymbolAddress((void**)&pehi,  g_ehi);
    cudaGetSymbolAddress((void**)&pelo,  g_elo);
    cudaGetSymbolAddress((void**)&pcwhi, g_cwhi);
    cudaGetSymbolAddress((void**)&pcwlo, g_cwlo);
    cudaGetSymbolAddress((void**)&pwkvhi, g_wkvhi);
    cudaGetSymbolAddress((void**)&pwkvlo, g_wkvlo);
    cudaGetSymbolAddress((void**)&pbkv,  g_bkv);

    // prep: sparse structure + weight prep (fused permute+split) + emb split
    k_build<<<NBR_, 256>>>(adj, pnbr, pcnt);
    k_wprep<<<3 * KP, 256>>>(gnnw, pwhi, pwlo);
    k_cwsplit<<<(C_IN * C_DIM + 255) / 256, 256>>>(cptW, pcwhi, pcwlo);
    k_wkvsplit<<<(KP * 400 + 255) / 256, 256>>>(wk, wv, bk, bv, pwkvhi, pwkvlo, pbkv);
    k_gsplit<<<(ROWS * C_IN + 255) / 256, 256>>>(emb, concepts, pehi, pelo);
    k_padzero<<<(ROWS * 24 + 255) / 256, 256>>>(pxhi, pxlo);

    // embedding: x = gelu(emb_g @ cptW + cptb) on tensor path; emits x + hi/lo
    {
        dim3 g(2, ROWS / 128);
        k_mma<32, true, true><<<g, 256>>>(pehi, pelo, pcwhi, pcwlo, cptb,
                                          px, C_DIM, C_DIM, pxhi, pxlo);
    }

    // 3 RGCN layers: mma GEMM -> fused sparse aggregate + split
    dim3 gMMA((RC + 127) / 128, ROWS / 128);   // 54 x 50
    k_mma<7, false, false><<<gMMA, 256>>>(pxhi, pxlo, pwhi + (size_t)0 * WT_L,
                                          pwlo + (size_t)0 * WT_L, nullptr, py, RC, RC,
                                          nullptr, nullptr);
    k_sagg<<<ROWS, 64>>>(py, pnbr, pcnt, px2, pxhi, pxlo);
    k_mma<7, false, false><<<gMMA, 256>>>(pxhi, pxlo, pwhi + (size_t)1 * WT_L,
                                          pwlo + (size_t)1 * WT_L, nullptr, py, RC, RC,
                                          nullptr, nullptr);
    k_sagg<<<ROWS, 64>>>(py, pnbr, pcnt, px, pxhi, pxlo);
    k_mma<7, false, false><<<gMMA, 256>>>(pxhi, pxlo, pwhi + (size_t)2 * WT_L,
                                          pwlo + (size_t)2 * WT_L, nullptr, py, RC, RC,
                                          nullptr, nullptr);
    k_sagg<<<ROWS, 64>>>(py, pnbr, pcnt, px2, pxhi, pxlo);   // final x in px2 + hi/lo

    // kv = x @ [wk|wv] + [bk|bv] on tensor path
    {
        dim3 g(4, ROWS / 128);
        k_mma<7, true, false><<<g, 256>>>(pxhi, pxlo, pwkvhi, pwkvlo, pbkv,
                                          pkv, 400, 400, nullptr, nullptr);
    }

    // q = sent @ wq + bq (fp32, tiny)
    {
        dim3 g(2, 1);
        k_gemm<false, true><<<g, 256>>>(sent, nullptr, SENT_DIM, wq, C_DIM, bq,
                                        pq, C_DIM, B_, C_DIM, SENT_DIM);
    }

    k_attn<<<B_, 256>>>(pq, pkv, lens, out, pgv);
    k_mlp<<<B_, 512>>>(pgv, sent, fcW0, fcb0, lng, lnb, fcW1, fcb1, out);
}

// round 15
// speedup vs baseline: 1.0287x; 1.0287x over previous
#include <cuda_runtime.h>
#include <cuda_bf16.h>
#include <math.h>
#include <stdint.h>

#define B_        32
#define N_NODE    200
#define N_REL     34
#define C_DIM     200
#define C_IN      1024
#define SENT_DIM  1024
#define FC_DIM    512
#define NBR_      (B_ * N_REL)            /* 1088 */
#define NN        (N_NODE * N_NODE)       /* 40000 */
#define RC        (N_REL * C_DIM)         /* 6800 */
#define ROWS      (B_ * N_NODE)           /* 6400 */
#define KP        224                     /* padded K for layer/kv tensor path */
#define WT_L      (KP * RC)               /* bf16 elems of layer W per layer */

// -------- device scratch (no allocations allowed) --------
__device__ float   g_x  [ROWS * C_DIM];
__device__ float   g_x2 [ROWS * C_DIM];
__device__ float   g_y  [(size_t)ROWS * RC];    // 174 MB
__device__ uint8_t g_nbr[(size_t)NBR_ * N_NODE * N_NODE];
__device__ int     g_cnt[NBR_ * N_NODE];
__device__ float   g_kv [ROWS * 400];           // fused k|v
__device__ float   g_q  [B_ * C_DIM];
__device__ float   g_gv [B_ * C_DIM];
// tensor-core operands (split bf16)
__device__ __nv_bfloat16 g_xhi[ROWS * KP];
__device__ __nv_bfloat16 g_xlo[ROWS * KP];
__device__ __nv_bfloat16 g_whi[3 * WT_L];
__device__ __nv_bfloat16 g_wlo[3 * WT_L];
__device__ __nv_bfloat16 g_ehi[ROWS * C_IN];    // gathered emb rows, split
__device__ __nv_bfloat16 g_elo[ROWS * C_IN];
__device__ __nv_bfloat16 g_cwhi[C_IN * C_DIM];  // cptW split
__device__ __nv_bfloat16 g_cwlo[C_IN * C_DIM];
__device__ __nv_bfloat16 g_wkvhi[KP * 400];     // [wk|wv] split, K padded
__device__ __nv_bfloat16 g_wkvlo[KP * 400];
__device__ float   g_bkv[400];

__device__ __forceinline__ float gelu_f(float x) {
    return 0.5f * x * (1.0f + erff(x * 0.70710678118654752f));
}

__device__ __forceinline__ uint32_t smem_u32(const void* p) {
    uint32_t a;
    asm("{ .reg .u64 t; cvta.to.shared.u64 t, %1; cvt.u32.u64 %0, t; }" : "=r"(a) : "l"(p));
    return a;
}
__device__ __forceinline__ void ldsm4(uint32_t* r, uint32_t addr) {
    asm volatile("ldmatrix.sync.aligned.m8n8.x4.shared.b16 {%0,%1,%2,%3}, [%4];"
                 : "=r"(r[0]), "=r"(r[1]), "=r"(r[2]), "=r"(r[3]) : "r"(addr));
}
__device__ __forceinline__ void ldsm4t(uint32_t* r, uint32_t addr) {
    asm volatile("ldmatrix.sync.aligned.m8n8.x4.trans.shared.b16 {%0,%1,%2,%3}, [%4];"
                 : "=r"(r[0]), "=r"(r[1]), "=r"(r[2]), "=r"(r[3]) : "r"(addr));
}
__device__ __forceinline__ void mma16816(float* c, const uint32_t* a, const uint32_t* b) {
    asm volatile(
        "mma.sync.aligned.m16n8k16.row.col.f32.bf16.bf16.f32 "
        "{%0,%1,%2,%3}, {%4,%5,%6,%7}, {%8,%9}, {%0,%1,%2,%3};"
        : "+f"(c[0]), "+f"(c[1]), "+f"(c[2]), "+f"(c[3])
        : "r"(a[0]), "r"(a[1]), "r"(a[2]), "r"(a[3]), "r"(b[0]), "r"(b[1]));
}

// ---------------------------------------------------------------------------
// Build in-edge lists.
// ---------------------------------------------------------------------------
__global__ void k_build(const float* __restrict__ adj, uint8_t* __restrict__ nbr,
                        int* __restrict__ cnt) {
    int br = blockIdx.x;
    int i = threadIdx.x;
    if (i < N_NODE) {
        const float* a = adj + (size_t)br * NN + i;
        uint8_t* nb = nbr + ((size_t)br * N_NODE + i) * N_NODE;
        int c = 0;
        for (int j = 0; j < N_NODE; j++)
            if (a[(size_t)j * N_NODE] != 0.f) nb[c++] = (uint8_t)j;
        cnt[br * N_NODE + i] = c;
    }
}

// ---------------------------------------------------------------------------
// Fused permute + split + K-pad of gnn_w:
// whi/wlo[l][k][r*200+o] = split(gw[l][k][o*34+r]);  rows k>=200 are zero.
// One block per (l, k) with k in 0..KP-1 (672 blocks).
// ---------------------------------------------------------------------------
__global__ void k_wprep(const float* __restrict__ gw,
                        __nv_bfloat16* __restrict__ hi, __nv_bfloat16* __restrict__ lo) {
    __shared__ float s[RC];
    int bid = blockIdx.x;
    int l = bid / KP, k = bid % KP;
    size_t dst = ((size_t)l * KP + k) * RC;
    if (k < C_DIM) {
        const float* src = gw + ((size_t)l * C_DIM + k) * RC;
        for (int i = threadIdx.x; i < RC; i += 256) s[i] = src[i];
        __syncthreads();
        for (int n = threadIdx.x; n < RC; n += 256) {
            int r = n / C_DIM, o = n % C_DIM;
            float v = s[o * N_REL + r];
            __nv_bfloat16 h = __float2bfloat16(v);
            hi[dst + n] = h;
            lo[dst + n] = __float2bfloat16(v - __bfloat162float(h));
        }
    } else {
        __nv_bfloat16 z = __float2bfloat16(0.f);
        for (int n = threadIdx.x; n < RC; n += 256) { hi[dst + n] = z; lo[dst + n] = z; }
    }
}

// ---------------------------------------------------------------------------
// Merged elementwise prep (one launch):
//   [0, 800)        cwsplit: split cptW [1024*200]
//   [800, 1150)     wkvsplit: [wk|wv] -> [224][400] split + bias concat
//   [1150, 26750)   gsplit: gather+split emb rows [ROWS][1024]
//   [26750, 27350)  padzero: zero K-pad cols 200..223 of xhi/xlo
// ---------------------------------------------------------------------------
__global__ void k_msplit(const float* __restrict__ cptW,
                         const float* __restrict__ wk, const float* __restrict__ wv,
                         const float* __restrict__ bk, const float* __restrict__ bv,
                         const float* __restrict__ emb, const int* __restrict__ concepts,
                         __nv_bfloat16* __restrict__ cwhi, __nv_bfloat16* __restrict__ cwlo,
                         __nv_bfloat16* __restrict__ wkvhi, __nv_bfloat16* __restrict__ wkvlo,
                         float* __restrict__ bkv,
                         __nv_bfloat16* __restrict__ ehi, __nv_bfloat16* __restrict__ elo,
                         __nv_bfloat16* __restrict__ xhi, __nv_bfloat16* __restrict__ xlo) {
    int bid = blockIdx.x;
    int t = threadIdx.x;
    if (bid < 800) {
        int idx = bid * 256 + t;
        if (idx < C_IN * C_DIM) {
            float v = cptW[idx];
            __nv_bfloat16 h = __float2bfloat16(v);
            cwhi[idx] = h;
            cwlo[idx] = __float2bfloat16(v - __bfloat162float(h));
        }
    } else if (bid < 1150) {
        int idx = (bid - 800) * 256 + t;
        if (idx < 400) bkv[idx] = (idx < C_DIM) ? bk[idx] : bv[idx - C_DIM];
        if (idx < KP * 400) {
            int k = idx / 400, n = idx % 400;
            float v = 0.f;
            if (k < C_DIM) v = (n < C_DIM) ? wk[k * C_DIM + n] : wv[k * C_DIM + (n - C_DIM)];
            __nv_bfloat16 h = __float2bfloat16(v);
            wkvhi[idx] = h;
            wkvlo[idx] = __float2bfloat16(v - __bfloat162float(h));
        }
    } else if (bid < 26750) {
        int idx = (bid - 1150) * 256 + t;
        if (idx < ROWS * C_IN) {
            int row = idx >> 10, k = idx & 1023;
            float v = emb[(size_t)concepts[row] * C_IN + k];
            __nv_bfloat16 h = __float2bfloat16(v);
            ehi[idx] = h;
            elo[idx] = __float2bfloat16(v - __bfloat162float(h));
        }
    } else {
        int idx = (bid - 26750) * 256 + t;
        if (idx < ROWS * 24) {
            int row = idx / 24, col = C_DIM + idx % 24;
            xhi[(size_t)row * KP + col] = __float2bfloat16(0.f);
            xlo[(size_t)row * KP + col] = __float2bfloat16(0.f);
        }
    }
}

// ---------------------------------------------------------------------------
// Generalized tensor-core GEMM (mma.sync bf16, split-precision 3-pass),
// single SMEM buffer with register prefetch (proven fastest config):
// out[m][n] = act(sum_k A[m][k] * W[k][n] + bias)
// 128x128 CTA tile, 8 warps (2M x 4N), each warp 64x32 via m16n8k16.
// KCH = k32-chunks per pass. SPLITOUT: GELU + emit bf16 hi/lo (stride KP).
// ---------------------------------------------------------------------------
template <int KCH, bool BIAS, bool SPLITOUT>
__global__ void __launch_bounds__(256)
k_mma(const __nv_bfloat16* __restrict__ xhi, const __nv_bfloat16* __restrict__ xlo,
      const __nv_bfloat16* __restrict__ whi, const __nv_bfloat16* __restrict__ wlo,
      const float* __restrict__ bias, float* __restrict__ out, int ldc, int N,
      __nv_bfloat16* __restrict__ ohi, __nv_bfloat16* __restrict__ olo) {
    const int KPA = KCH * 32;
    __shared__ __align__(16) __nv_bfloat16 sA[128][40];    // k-chunk 32, +8 pad
    __shared__ __align__(16) __nv_bfloat16 sB[32][136];    // n 128, +8 pad
    const int t = threadIdx.x;
    const int lane = t & 31, wid = t >> 5;
    const int wm = (wid & 1) * 64, wn = (wid >> 1) * 32;
    const int m0 = blockIdx.y * 128, n0 = blockIdx.x * 128;

    // global loader coords
    const int arow = t >> 1, acol = (t & 1) * 16;    // A: 2 x 16B per thread
    const int brow = t >> 3, bcol = (t & 7) * 16;    // B: 2 x 16B per thread
    const bool bg0 = (n0 + bcol) < N;
    const bool bg1 = (n0 + bcol + 8) < N;

    // ldmatrix smem addresses (bytes)
    const uint32_t sa_b = smem_u32(&sA[0][0]);
    const uint32_t sb_b = smem_u32(&sB[0][0]);
    uint32_t saAddr[4], sbAddr[2];
    #pragma unroll
    for (int mi = 0; mi < 4; mi++)
        saAddr[mi] = sa_b + ((wm + mi * 16 + (lane & 15)) * 40 + (lane >> 4) * 8) * 2;
    #pragma unroll
    for (int nb = 0; nb < 2; nb++)
        sbAddr[nb] = sb_b + ((lane & 15) * 136 + wn + nb * 16 + (lane >> 4) * 8) * 2;

    float acc[4][4][4];
    #pragma unroll
    for (int i = 0; i < 4; i++)
        #pragma unroll
        for (int j = 0; j < 4; j++)
            #pragma unroll
            for (int q = 0; q < 4; q++) acc[i][j][q] = 0.f;

    const uint4 z4 = make_uint4(0, 0, 0, 0);
    uint4 aP0, aP1, bP0, bP1;

    // prefetch chunk 0
    {
        const __nv_bfloat16* ar = xhi + (size_t)(m0 + arow) * KPA + acol;
        aP0 = *reinterpret_cast<const uint4*>(ar);
        aP1 = *reinterpret_cast<const uint4*>(ar + 8);
        const __nv_bfloat16* br = whi + (size_t)brow * N + n0 + bcol;
        bP0 = bg0 ? *reinterpret_cast<const uint4*>(br) : z4;
        bP1 = bg1 ? *reinterpret_cast<const uint4*>(br + 8) : z4;
    }

    const int NITER = 3 * KCH;
    for (int it = 0; it < NITER; it++) {
        __syncthreads();
        *reinterpret_cast<uint4*>(&sA[arow][acol])     = aP0;
        *reinterpret_cast<uint4*>(&sA[arow][acol + 8]) = aP1;
        *reinterpret_cast<uint4*>(&sB[brow][bcol])     = bP0;
        *reinterpret_cast<uint4*>(&sB[brow][bcol + 8]) = bP1;

        if (it + 1 < NITER) {
            int p = (it + 1) / KCH, kc = ((it + 1) % KCH) * 32;
            const __nv_bfloat16* Ap = (p < 2) ? xhi : xlo;
            const __nv_bfloat16* Bp = (p == 1) ? wlo : whi;
            const __nv_bfloat16* ar = Ap + (size_t)(m0 + arow) * KPA + kc + acol;
            aP0 = *reinterpret_cast<const uint4*>(ar);
            aP1 = *reinterpret_cast<const uint4*>(ar + 8);
            const __nv_bfloat16* br = Bp + (size_t)(kc + brow) * N + n0 + bcol;
            bP0 = bg0 ? *reinterpret_cast<const uint4*>(br) : z4;
            bP1 = bg1 ? *reinterpret_cast<const uint4*>(br + 8) : z4;
        }
        __syncthreads();

        #pragma unroll
        for (int ks = 0; ks < 2; ks++) {
            uint32_t bf[8];
            ldsm4t(bf,     sbAddr[0] + ks * 4352);   // 16 rows * 272B
            ldsm4t(bf + 4, sbAddr[1] + ks * 4352);
            uint32_t af[4][4];
            #pragma unroll
            for (int mi = 0; mi < 4; mi++)
                ldsm4(af[mi], saAddr[mi] + ks * 32);
            #pragma unroll
            for (int mi = 0; mi < 4; mi++) {
                mma16816(acc[mi][0], af[mi], bf + 0);
                mma16816(acc[mi][1], af[mi], bf + 2);
                mma16816(acc[mi][2], af[mi], bf + 4);
                mma16816(acc[mi][3], af[mi], bf + 6);
            }
        }
    }

    // epilogue: c-frag rows = lane>>2 (+8), cols = (lane&3)*2 (+1)
    #pragma unroll
    for (int mi = 0; mi < 4; mi++) {
        int r = m0 + wm + mi * 16 + (lane >> 2);
        #pragma unroll
        for (int nj = 0; nj < 4; nj++) {
            int c = n0 + wn + nj * 8 + (lane & 3) * 2;
            if (c < N) {
                #pragma unroll
                for (int half = 0; half < 2; half++) {
                    int rr = r + half * 8;
                    float v0 = acc[mi][nj][half * 2 + 0];
                    float v1 = acc[mi][nj][half * 2 + 1];
                    if (BIAS) { v0 += bias[c]; v1 += bias[c + 1]; }
                    if (SPLITOUT) {
                        v0 = gelu_f(v0); v1 = gelu_f(v1);
                        __align__(4) __nv_bfloat16 h2[2], l2[2];
                        h2[0] = __float2bfloat16(v0);
                        h2[1] = __float2bfloat16(v1);
                        l2[0] = __float2bfloat16(v0 - __bfloat162float(h2[0]));
                        l2[1] = __float2bfloat16(v1 - __bfloat162float(h2[1]));
                        *reinterpret_cast<uint32_t*>(&ohi[(size_t)rr * KP + c]) =
                            *reinterpret_cast<const uint32_t*>(h2);
                        *reinterpret_cast<uint32_t*>(&olo[(size_t)rr * KP + c]) =
                            *reinterpret_cast<const uint32_t*>(l2);
                    }
                    *reinterpret_cast<float2*>(&out[(size_t)rr * ldc + c]) =
                        make_float2(v0, v1);
                }
            }
        }
    }
}

// ---------------------------------------------------------------------------
// fp32 tiled GEMM (q only): 128x128x16, 8x8 microtiles, conflict-free.
// ---------------------------------------------------------------------------
template <bool GELU, bool BIAS>
__global__ void __launch_bounds__(256, 2)
k_gemm(const float* __restrict__ A, const int* __restrict__ gather, int lda,
       const float* __restrict__ Bm, int ldb, const float* __restrict__ bias,
       float* __restrict__ C, int ldc, int M, int N, int K) {
    __shared__ __align__(16) float sA[16][132];
    __shared__ __align__(16) float sB[16][128];
    const int t = threadIdx.x;
    const int n0 = blockIdx.x * 128, m0 = blockIdx.y * 128;
    const int rowA = t >> 1, kqA = (t & 1) * 8;
    const int kkB = t >> 4, nqB = (t & 15) * 4;
    const int tr4 = (t >> 4) * 4, tc4 = (t & 15) * 4;

    const int gm = m0 + rowA;
    const float* arow = nullptr;
    if (gm < M) arow = A + (size_t)(gather ? gather[gm] : gm) * lda;
    const bool bn0 = (n0 + nqB) < N;
    const bool bn1 = (n0 + 64 + nqB) < N;

    const float4 z4 = make_float4(0.f, 0.f, 0.f, 0.f);
    float4 aR0 = z4, aR1 = z4, bR0 = z4, bR1 = z4;
    {
        int ka = kqA;
        if (arow && ka < K) {
            aR0 = *reinterpret_cast<const float4*>(arow + ka);
            aR1 = *reinterpret_cast<const float4*>(arow + ka + 4);
        }
        int kb = kkB;
        if (kb < K) {
            const float* bp = Bm + (size_t)kb * ldb + n0 + nqB;
            if (bn0) bR0 = *reinterpret_cast<const float4*>(bp);
            if (bn1) bR1 = *reinterpret_cast<const float4*>(bp + 64);
        }
    }

    float acc[8][8] = {};
    for (int k0 = 0; k0 < K; k0 += 16) {
        __syncthreads();
        sA[kqA + 0][rowA] = aR0.x; sA[kqA + 1][rowA] = aR0.y;
        sA[kqA + 2][rowA] = aR0.z; sA[kqA + 3][rowA] = aR0.w;
        sA[kqA + 4][rowA] = aR1.x; sA[kqA + 5][rowA] = aR1.y;
        sA[kqA + 6][rowA] = aR1.z; sA[kqA + 7][rowA] = aR1.w;
        *reinterpret_cast<float4*>(&sB[kkB][nqB])      = bR0;
        *reinterpret_cast<float4*>(&sB[kkB][64 + nqB]) = bR1;

        int k1 = k0 + 16;
        if (k1 < K) {
            aR0 = z4; aR1 = z4; bR0 = z4; bR1 = z4;
            int ka = k1 + kqA;
            if (arow && ka < K) {
                aR0 = *reinterpret_cast<const float4*>(arow + ka);
                aR1 = *reinterpret_cast<const float4*>(arow + ka + 4);
            }
            int kb = k1 + kkB;
            if (kb < K) {
                const float* bp = Bm + (size_t)kb * ldb + n0 + nqB;
                if (bn0) bR0 = *reinterpret_cast<const float4*>(bp);
                if (bn1) bR1 = *reinterpret_cast<const float4*>(bp + 64);
            }
        }
        __syncthreads();

        #pragma unroll
        for (int kk = 0; kk < 16; kk++) {
            float4 a0 = *reinterpret_cast<const float4*>(&sA[kk][tr4]);
            float4 a1 = *reinterpret_cast<const float4*>(&sA[kk][64 + tr4]);
            float4 b0 = *reinterpret_cast<const float4*>(&sB[kk][tc4]);
            float4 b1 = *reinterpret_cast<const float4*>(&sB[kk][64 + tc4]);
            const float av[8] = {a0.x, a0.y, a0.z, a0.w, a1.x, a1.y, a1.z, a1.w};
            const float bv[8] = {b0.x, b0.y, b0.z, b0.w, b1.x, b1.y, b1.z, b1.w};
            #pragma unroll
            for (int i = 0; i < 8; i++)
                #pragma unroll
                for (int j = 0; j < 8; j++)
                    acc[i][j] += av[i] * bv[j];
        }
    }

    #pragma unroll
    for (int i = 0; i < 8; i++) {
        int m = m0 + ((i < 4) ? (tr4 + i) : (64 + tr4 + i - 4));
        if (m >= M) continue;
        #pragma unroll
        for (int jh = 0; jh < 2; jh++) {
            int n = n0 + jh * 64 + tc4;
            if (n >= N) continue;
            float4 v;
            v.x = acc[i][jh * 4 + 0]; v.y = acc[i][jh * 4 + 1];
            v.z = acc[i][jh * 4 + 2]; v.w = acc[i][jh * 4 + 3];
            if (BIAS) {
                v.x += bias[n + 0]; v.y += bias[n + 1];
                v.z += bias[n + 2]; v.w += bias[n + 3];
            }
            if (GELU) {
                v.x = gelu_f(v.x); v.y = gelu_f(v.y);
                v.z = gelu_f(v.z); v.w = gelu_f(v.w);
            }
            *reinterpret_cast<float4*>(&C[(size_t)m * ldc + n]) = v;
        }
    }
}

// ---------------------------------------------------------------------------
// Sparse aggregate + GELU, fused with bf16 hi/lo split for the next layer.
// ---------------------------------------------------------------------------
__global__ void k_sagg(const float* __restrict__ y, const uint8_t* __restrict__ nbr,
                       const int* __restrict__ cnt, float* __restrict__ xout,
                       __nv_bfloat16* __restrict__ hi, __nv_bfloat16* __restrict__ lo) {
    int bi = blockIdx.x;
    int b = bi / N_NODE, i = bi % N_NODE;
    int t = threadIdx.x;                 // 64
    __shared__ uint8_t sj[N_NODE];
    float4 acc = make_float4(0.f, 0.f, 0.f, 0.f);
    const float* yb = y + (size_t)b * N_NODE * RC;
    for (int r = 0; r < N_REL; r++) {
        int br = b * N_REL + r;
        int c = cnt[br * N_NODE + i];
        const uint8_t* base = nbr + ((size_t)br * N_NODE + i) * N_NODE;
        for (int s = t; s < c; s += 64) sj[s] = base[s];
        __syncthreads();
        if (t < 50) {
            const float* yr = yb + r * C_DIM + t * 4;
            float4 tmp = make_float4(0.f, 0.f, 0.f, 0.f);
            #pragma unroll 4
            for (int s = 0; s < c; s++) {
                float4 v = *reinterpret_cast<const float4*>(yr + (size_t)sj[s] * RC);
                tmp.x += v.x; tmp.y += v.y; tmp.z += v.z; tmp.w += v.w;
            }
            float inv = 1.0f / (float)c;
            acc.x += tmp.x * inv; acc.y += tmp.y * inv;
            acc.z += tmp.z * inv; acc.w += tmp.w * inv;
        }
        __syncthreads();
    }
    if (t < 50) {
        float o[4];
        o[0] = gelu_f(acc.x); o[1] = gelu_f(acc.y);
        o[2] = gelu_f(acc.z); o[3] = gelu_f(acc.w);
        *reinterpret_cast<float4*>(&xout[(size_t)bi * C_DIM + t * 4]) =
            make_float4(o[0], o[1], o[2], o[3]);
        __align__(8) __nv_bfloat16 h4[4], l4[4];
        #pragma unroll
        for (int j = 0; j < 4; j++) {
            __nv_bfloat16 h = __float2bfloat16(o[j]);
            h4[j] = h;
            l4[j] = __float2bfloat16(o[j] - __bfloat162float(h));
        }
        *reinterpret_cast<uint2*>(&hi[(size_t)bi * KP + t * 4]) = *reinterpret_cast<const uint2*>(h4);
        *reinterpret_cast<uint2*>(&lo[(size_t)bi * KP + t * 4]) = *reinterpret_cast<const uint2*>(l4);
    } else if (t < 56) {
        int col = C_DIM + (t - 50) * 4;   // 200..220, zero the K pad
        uint2 z = make_uint2(0, 0);
        *reinterpret_cast<uint2*>(&hi[(size_t)bi * KP + col]) = z;
        *reinterpret_cast<uint2*>(&lo[(size_t)bi * KP + col]) = z;
    }
}

// ---------------------------------------------------------------------------
// Attention pooling; k/v fused in one buffer with row stride 400 (k@0, v@200).
// ---------------------------------------------------------------------------
__global__ void k_attn(const float* __restrict__ q, const float* __restrict__ kv,
                       const int* __restrict__ lens,
                       float* __restrict__ out, float* __restrict__ gv) {
    int b = blockIdx.x;
    int t = threadIdx.x;   // 256
    __shared__ float sq[C_DIM];
    __shared__ float sa[2][N_NODE];
    __shared__ float red[256];
    if (t < C_DIM) sq[t] = q[b * C_DIM + t];
    __syncthreads();
    int len = lens[b];
    for (int h = 0; h < 2; h++) {
        float s = -INFINITY;
        if (t < N_NODE && t < len) {
            float acc = 0.f;
            const float* kr = kv + ((size_t)(b * N_NODE + t)) * 400 + h * 100;
            #pragma unroll 4
            for (int d = 0; d < 100; d++) acc += sq[h * 100 + d] * kr[d];
            s = acc * 0.1f;
        }
        red[t] = s;
        __syncthreads();
        for (int off = 128; off > 0; off >>= 1) {
            if (t < off) red[t] = fmaxf(red[t], red[t + off]);
            __syncthreads();
        }
        float mx = red[0];
        __syncthreads();
        float e = (t < N_NODE && t < len) ? expf(s - mx) : 0.f;
        red[t] = e;
        __syncthreads();
        for (int off = 128; off > 0; off >>= 1) {
            if (t < off) red[t] += red[t + off];
            __syncthreads();
        }
        float inv = 1.f / red[0];
        __syncthreads();
        if (t < N_NODE) {
            float a = e * inv;
            sa[h][t] = a;
            out[32 + ((size_t)(h * B_ + b)) * N_NODE + t] = a;
        }
        __syncthreads();
    }
    if (t < C_DIM) {
        int h = t / 100, d = t % 100;
        float g = 0.f;
        for (int l = 0; l < N_NODE; l++)
            g += sa[h][l] * kv[((size_t)(b * N_NODE + l)) * 400 + 200 + h * 100 + d];
        gv[b * C_DIM + t] = g;
    }
}

// ---------------------------------------------------------------------------
// MLP readout.
// ---------------------------------------------------------------------------
__global__ void k_mlp(const float* __restrict__ gv, const float* __restrict__ sent,
                      const float* __restrict__ W0, const float* __restrict__ b0,
                      const float* __restrict__ lng, const float* __restrict__ lnb,
                      const float* __restrict__ W1, const float* __restrict__ b1,
                      float* __restrict__ out) {
    int b = blockIdx.x;
    int t = threadIdx.x;   // 512
    const int ZD = C_DIM + SENT_DIM;
    __shared__ float zz[C_DIM + SENT_DIM];
    __shared__ float red[512];
    for (int i = t; i < ZD; i += 512)
        zz[i] = (i < C_DIM) ? gv[b * C_DIM + i] : sent[(size_t)b * SENT_DIM + (i - C_DIM)];
    __syncthreads();
    float acc = b0[t];
    #pragma unroll 4
    for (int k = 0; k < ZD; k++) acc += zz[k] * W0[(size_t)k * FC_DIM + t];
    red[t] = acc; __syncthreads();
    for (int off = 256; off > 0; off >>= 1) { if (t < off) red[t] += red[t + off]; __syncthreads(); }
    float mu = red[0] * (1.f / FC_DIM);
    __syncthreads();
    float d = acc - mu;
    red[t] = d * d; __syncthreads();
    for (int off = 256; off > 0; off >>= 1) { if (t < off) red[t] += red[t + off]; __syncthreads(); }
    float var = red[0] * (1.f / FC_DIM);
    __syncthreads();
    float h1 = gelu_f(d * rsqrtf(var + 1e-5f) * lng[t] + lnb[t]);
    red[t] = h1 * W1[t]; __syncthreads();
    for (int off = 256; off > 0; off >>= 1) { if (t < off) red[t] += red[t + off]; __syncthreads(); }
    if (t == 0) out[b] = red[0] + b1[0];
}

// ---------------------------------------------------------------------------
extern "C" void kernel_launch(void* const* d_in, const int* in_sizes, int n_in,
                              void* d_out, int out_size) {
    const float* sent     = (const float*)d_in[0];
    const int*   concepts = (const int*)  d_in[1];
    const float* adj      = (const float*)d_in[2];
    const int*   lens     = (const int*)  d_in[3];
    const float* emb      = (const float*)d_in[4];
    const float* cptW     = (const float*)d_in[5];
    const float* cptb     = (const float*)d_in[6];
    const float* gnnw     = (const float*)d_in[7];
    const float* wq       = (const float*)d_in[8];
    const float* bq       = (const float*)d_in[9];
    const float* wk       = (const float*)d_in[10];
    const float* bk       = (const float*)d_in[11];
    const float* wv       = (const float*)d_in[12];
    const float* bv       = (const float*)d_in[13];
    const float* fcW0     = (const float*)d_in[14];
    const float* fcb0     = (const float*)d_in[15];
    const float* lng      = (const float*)d_in[16];
    const float* lnb      = (const float*)d_in[17];
    const float* fcW1     = (const float*)d_in[18];
    const float* fcb1     = (const float*)d_in[19];
    float* out = (float*)d_out;

    float *px, *px2, *py, *pkv, *pq, *pgv, *pbkv;
    __nv_bfloat16 *pxhi, *pxlo, *pwhi, *pwlo, *pehi, *pelo, *pcwhi, *pcwlo, *pwkvhi, *pwkvlo;
    uint8_t* pnbr; int* pcnt;
    cudaGetSymbolAddress((void**)&px,    g_x);
    cudaGetSymbolAddress((void**)&px2,   g_x2);
    cudaGetSymbolAddress((void**)&py,    g_y);
    cudaGetSymbolAddress((void**)&pnbr,  g_nbr);
    cudaGetSymbolAddress((void**)&pcnt,  g_cnt);
    cudaGetSymbolAddress((void**)&pkv,   g_kv);
    cudaGetSymbolAddress((void**)&pq,    g_q);
    cudaGetSymbolAddress((void**)&pgv,   g_gv);
    cudaGetSymbolAddress((void**)&pxhi,  g_xhi);
    cudaGetSymbolAddress((void**)&pxlo,  g_xlo);
    cudaGetSymbolAddress((void**)&pwhi,  g_whi);
    cudaGetSymbolAddress((void**)&pwlo,  g_wlo);
    cudaGetSymbolAddress((void**)&pehi,  g_ehi);
    cudaGetSymbolAddress((void**)&pelo,  g_elo);
    cudaGetSymbolAddress((void**)&pcwhi, g_cwhi);
    cudaGetSymbolAddress((void**)&pcwlo, g_cwlo);
    cudaGetSymbolAddress((void**)&pwkvhi, g_wkvhi);
    cudaGetSymbolAddress((void**)&pwkvlo, g_wkvlo);
    cudaGetSymbolAddress((void**)&pbkv,  g_bkv);

    // [0] merged elementwise prep
    k_msplit<<<27350, 256>>>(cptW, wk, wv, bk, bv, emb, concepts,
                             pcwhi, pcwlo, pwkvhi, pwkvlo, pbkv,
                             pehi, pelo, pxhi, pxlo);
    // [1] layer-weight prep
    k_wprep<<<3 * KP, 256>>>(gnnw, pwhi, pwlo);
    // [2] embedding mma (emits x + hi/lo)
    {
        dim3 g(2, ROWS / 128);
        k_mma<32, true, true><<<g, 256>>>(pehi, pelo, pcwhi, pcwlo, cptb,
                                          px, C_DIM, C_DIM, pxhi, pxlo);
    }
    // [3] layer 0 mma  <-- ncu capture lands here (launch index 3)
    dim3 gMMA((RC + 127) / 128, ROWS / 128);   // 54 x 50
    k_mma<7, false, false><<<gMMA, 256>>>(pxhi, pxlo, pwhi + (size_t)0 * WT_L,
                                          pwlo + (size_t)0 * WT_L, nullptr, py, RC, RC,
                                          nullptr, nullptr);
    // [4] sparse structure (needed before first sagg)
    k_build<<<NBR_, 256>>>(adj, pnbr, pcnt);
    // [5..] rest of the pipeline
    k_sagg<<<ROWS, 64>>>(py, pnbr, pcnt, px2, pxhi, pxlo);
    k_mma<7, false, false><<<gMMA, 256>>>(pxhi, pxlo, pwhi + (size_t)1 * WT_L,
                                          pwlo + (size_t)1 * WT_L, nullptr, py, RC, RC,
                                          nullptr, nullptr);
    k_sagg<<<ROWS, 64>>>(py, pnbr, pcnt, px, pxhi, pxlo);
    k_mma<7, false, false><<<gMMA, 256>>>(pxhi, pxlo, pwhi + (size_t)2 * WT_L,
                                          pwlo + (size_t)2 * WT_L, nullptr, py, RC, RC,
                                          nullptr, nullptr);
    k_sagg<<<ROWS, 64>>>(py, pnbr, pcnt, px2, pxhi, pxlo);   // final x in px2 + hi/lo

    // kv = x @ [wk|wv] + [bk|bv] on tensor path
    {
        dim3 g(4, ROWS / 128);
        k_mma<7, true, false><<<g, 256>>>(pxhi, pxlo, pwkvhi, pwkvlo, pbkv,
                                          pkv, 400, 400, nullptr, nullptr);
    }
    // q = sent @ wq + bq (fp32, tiny)
    {
        dim3 g(2, 1);
        k_gemm<false, true><<<g, 256>>>(sent, nullptr, SENT_DIM, wq, C_DIM, bq,
                                        pq, C_DIM, B_, C_DIM, SENT_DIM);
    }

    k_attn<<<B_, 256>>>(pq, pkv, lens, out, pgv);
    k_mlp<<<B_, 512>>>(pgv, sent, fcW0, fcb0, lng, lnb, fcW1, fcb1, out);
}

// round 16
// speedup vs baseline: 1.2217x; 1.1876x over previous
#include <cuda_runtime.h>
#include <cuda_bf16.h>
#include <math.h>
#include <stdint.h>

#define B_        32
#define N_NODE    200
#define N_REL     34
#define C_DIM     200
#define C_IN      1024
#define SENT_DIM  1024
#define FC_DIM    512
#define NBR_      (B_ * N_REL)            /* 1088 */
#define NN        (N_NODE * N_NODE)       /* 40000 */
#define RC        (N_REL * C_DIM)         /* 6800 */
#define ROWS      (B_ * N_NODE)           /* 6400 */
#define KP        224                     /* padded K for layer/kv tensor path */
#define WT_L      (KP * RC)               /* bf16 elems of layer W per layer */

// -------- device scratch (no allocations allowed) --------
__device__ float   g_x  [ROWS * C_DIM];
__device__ float   g_x2 [ROWS * C_DIM];
__device__ float   g_y  [(size_t)ROWS * RC];    // 174 MB
__device__ uint8_t g_nbr[(size_t)NBR_ * N_NODE * N_NODE];
__device__ int     g_cnt[NBR_ * N_NODE];
__device__ float   g_kv [ROWS * 400];           // fused k|v
__device__ float   g_q  [B_ * C_DIM];
__device__ float   g_gv [B_ * C_DIM];
// tensor-core operands (split bf16)
__device__ __nv_bfloat16 g_xhi[ROWS * KP];
__device__ __nv_bfloat16 g_xlo[ROWS * KP];
__device__ __nv_bfloat16 g_whi[3 * WT_L];
__device__ __nv_bfloat16 g_wlo[3 * WT_L];
__device__ __nv_bfloat16 g_ehi[ROWS * C_IN];    // gathered emb rows, split
__device__ __nv_bfloat16 g_elo[ROWS * C_IN];
__device__ __nv_bfloat16 g_cwhi[C_IN * C_DIM];  // cptW split
__device__ __nv_bfloat16 g_cwlo[C_IN * C_DIM];
__device__ __nv_bfloat16 g_wkvhi[KP * 400];     // [wk|wv] split, K padded
__device__ __nv_bfloat16 g_wkvlo[KP * 400];
__device__ float   g_bkv[400];

__device__ __forceinline__ float gelu_f(float x) {
    return 0.5f * x * (1.0f + erff(x * 0.70710678118654752f));
}

__device__ __forceinline__ uint32_t smem_u32(const void* p) {
    uint32_t a;
    asm("{ .reg .u64 t; cvta.to.shared.u64 t, %1; cvt.u32.u64 %0, t; }" : "=r"(a) : "l"(p));
    return a;
}
__device__ __forceinline__ void ldsm4(uint32_t* r, uint32_t addr) {
    asm volatile("ldmatrix.sync.aligned.m8n8.x4.shared.b16 {%0,%1,%2,%3}, [%4];"
                 : "=r"(r[0]), "=r"(r[1]), "=r"(r[2]), "=r"(r[3]) : "r"(addr));
}
__device__ __forceinline__ void ldsm4t(uint32_t* r, uint32_t addr) {
    asm volatile("ldmatrix.sync.aligned.m8n8.x4.trans.shared.b16 {%0,%1,%2,%3}, [%4];"
                 : "=r"(r[0]), "=r"(r[1]), "=r"(r[2]), "=r"(r[3]) : "r"(addr));
}
__device__ __forceinline__ void mma16816(float* c, const uint32_t* a, const uint32_t* b) {
    asm volatile(
        "mma.sync.aligned.m16n8k16.row.col.f32.bf16.bf16.f32 "
        "{%0,%1,%2,%3}, {%4,%5,%6,%7}, {%8,%9}, {%0,%1,%2,%3};"
        : "+f"(c[0]), "+f"(c[1]), "+f"(c[2]), "+f"(c[3])
        : "r"(a[0]), "r"(a[1]), "r"(a[2]), "r"(a[3]), "r"(b[0]), "r"(b[1]));
}
__device__ __forceinline__ void cp16(uint32_t dst, const void* src) {
    asm volatile("cp.async.ca.shared.global [%0], [%1], 16;" :: "r"(dst), "l"(src));
}
__device__ __forceinline__ void cp_commit() {
    asm volatile("cp.async.commit_group;" ::: "memory");
}
__device__ __forceinline__ void cp_wait0() {
    asm volatile("cp.async.wait_group 0;" ::: "memory");
}

// ---------------------------------------------------------------------------
// Build in-edge lists.
// ---------------------------------------------------------------------------
__global__ void k_build(const float* __restrict__ adj, uint8_t* __restrict__ nbr,
                        int* __restrict__ cnt) {
    int br = blockIdx.x;
    int i = threadIdx.x;
    if (i < N_NODE) {
        const float* a = adj + (size_t)br * NN + i;
        uint8_t* nb = nbr + ((size_t)br * N_NODE + i) * N_NODE;
        int c = 0;
        for (int j = 0; j < N_NODE; j++)
            if (a[(size_t)j * N_NODE] != 0.f) nb[c++] = (uint8_t)j;
        cnt[br * N_NODE + i] = c;
    }
}

// ---------------------------------------------------------------------------
// Fused permute + split + K-pad of gnn_w.
// ---------------------------------------------------------------------------
__global__ void k_wprep(const float* __restrict__ gw,
                        __nv_bfloat16* __restrict__ hi, __nv_bfloat16* __restrict__ lo) {
    __shared__ float s[RC];
    int bid = blockIdx.x;
    int l = bid / KP, k = bid % KP;
    size_t dst = ((size_t)l * KP + k) * RC;
    if (k < C_DIM) {
        const float* src = gw + ((size_t)l * C_DIM + k) * RC;
        for (int i = threadIdx.x; i < RC; i += 256) s[i] = src[i];
        __syncthreads();
        for (int n = threadIdx.x; n < RC; n += 256) {
            int r = n / C_DIM, o = n % C_DIM;
            float v = s[o * N_REL + r];
            __nv_bfloat16 h = __float2bfloat16(v);
            hi[dst + n] = h;
            lo[dst + n] = __float2bfloat16(v - __bfloat162float(h));
        }
    } else {
        __nv_bfloat16 z = __float2bfloat16(0.f);
        for (int n = threadIdx.x; n < RC; n += 256) { hi[dst + n] = z; lo[dst + n] = z; }
    }
}

// ---------------------------------------------------------------------------
// Merged elementwise prep (one launch).
// ---------------------------------------------------------------------------
__global__ void k_msplit(const float* __restrict__ cptW,
                         const float* __restrict__ wk, const float* __restrict__ wv,
                         const float* __restrict__ bk, const float* __restrict__ bv,
                         const float* __restrict__ emb, const int* __restrict__ concepts,
                         __nv_bfloat16* __restrict__ cwhi, __nv_bfloat16* __restrict__ cwlo,
                         __nv_bfloat16* __restrict__ wkvhi, __nv_bfloat16* __restrict__ wkvlo,
                         float* __restrict__ bkv,
                         __nv_bfloat16* __restrict__ ehi, __nv_bfloat16* __restrict__ elo,
                         __nv_bfloat16* __restrict__ xhi, __nv_bfloat16* __restrict__ xlo) {
    int bid = blockIdx.x;
    int t = threadIdx.x;
    if (bid < 800) {
        int idx = bid * 256 + t;
        if (idx < C_IN * C_DIM) {
            float v = cptW[idx];
            __nv_bfloat16 h = __float2bfloat16(v);
            cwhi[idx] = h;
            cwlo[idx] = __float2bfloat16(v - __bfloat162float(h));
        }
    } else if (bid < 1150) {
        int idx = (bid - 800) * 256 + t;
        if (idx < 400) bkv[idx] = (idx < C_DIM) ? bk[idx] : bv[idx - C_DIM];
        if (idx < KP * 400) {
            int k = idx / 400, n = idx % 400;
            float v = 0.f;
            if (k < C_DIM) v = (n < C_DIM) ? wk[k * C_DIM + n] : wv[k * C_DIM + (n - C_DIM)];
            __nv_bfloat16 h = __float2bfloat16(v);
            wkvhi[idx] = h;
            wkvlo[idx] = __float2bfloat16(v - __bfloat162float(h));
        }
    } else if (bid < 26750) {
        int idx = (bid - 1150) * 256 + t;
        if (idx < ROWS * C_IN) {
            int row = idx >> 10, k = idx & 1023;
            float v = emb[(size_t)concepts[row] * C_IN + k];
            __nv_bfloat16 h = __float2bfloat16(v);
            ehi[idx] = h;
            elo[idx] = __float2bfloat16(v - __bfloat162float(h));
        }
    } else {
        int idx = (bid - 26750) * 256 + t;
        if (idx < ROWS * 24) {
            int row = idx / 24, col = C_DIM + idx % 24;
            xhi[(size_t)row * KP + col] = __float2bfloat16(0.f);
            xlo[(size_t)row * KP + col] = __float2bfloat16(0.f);
        }
    }
}

// ---------------------------------------------------------------------------
// FUSED split-precision tensor-core GEMM (one k-chunk pass, 3 combos/chunk):
//   out[m][n] = act( sum_k (Ah+Al)[m][k] * (Bh+Bl)[k][n] + bias ),  AlBl dropped
// 2-stage cp.async pipeline, 4 tiles (Ah,Al,Bh,Bl) per stage.
// 128x128 CTA tile, 8 warps (2M x 4N). KCH = number of k32 chunks.
// Dynamic SMEM: 2 * 37888 = 75776 bytes.
// ---------------------------------------------------------------------------
#define SM_AH 0u
#define SM_AL 10240u
#define SM_BH 20480u
#define SM_BL 29184u
#define SM_ST 37888u
template <int KCH, bool BIAS, bool SPLITOUT>
__global__ void __launch_bounds__(256)
k_mma(const __nv_bfloat16* __restrict__ xhi, const __nv_bfloat16* __restrict__ xlo,
      const __nv_bfloat16* __restrict__ whi, const __nv_bfloat16* __restrict__ wlo,
      const float* __restrict__ bias, float* __restrict__ out, int ldc, int N,
      __nv_bfloat16* __restrict__ ohi, __nv_bfloat16* __restrict__ olo) {
    const int KPA = KCH * 32;
    extern __shared__ char smem[];
    const uint32_t sb = smem_u32(smem);
    const int t = threadIdx.x;
    const int lane = t & 31, wid = t >> 5;
    const int wm = (wid & 1) * 64, wn = (wid >> 1) * 32;
    const int m0 = blockIdx.y * 128, n0 = blockIdx.x * 128;

    // ldmatrix relative addresses (within a tile)
    uint32_t saRel[4], sbRel[2];
    #pragma unroll
    for (int mi = 0; mi < 4; mi++)
        saRel[mi] = ((wm + mi * 16 + (lane & 15)) * 40 + (lane >> 4) * 8) * 2;
    #pragma unroll
    for (int nb = 0; nb < 2; nb++)
        sbRel[nb] = ((lane & 15) * 136 + wn + nb * 16 + (lane >> 4) * 8) * 2;

    float acc[4][4][4];
    #pragma unroll
    for (int i = 0; i < 4; i++)
        #pragma unroll
        for (int j = 0; j < 4; j++)
            #pragma unroll
            for (int q = 0; q < 4; q++) acc[i][j][q] = 0.f;

    // zero OOB B cells once (both stages; cp.async never writes them)
    #pragma unroll
    for (int p = 0; p < 2; p++) {
        int idx = p * 256 + t;
        int r = idx >> 4, s8 = idx & 15;
        if (n0 + s8 * 8 >= N) {
            const uint4 z = make_uint4(0, 0, 0, 0);
            uint32_t off = (uint32_t)(r * 272 + s8 * 16);
            *reinterpret_cast<uint4*>(smem + SM_BH + off) = z;
            *reinterpret_cast<uint4*>(smem + SM_BL + off) = z;
            *reinterpret_cast<uint4*>(smem + SM_ST + SM_BH + off) = z;
            *reinterpret_cast<uint4*>(smem + SM_ST + SM_BL + off) = z;
        }
    }

    auto issue = [&](int it) {
        const uint32_t sbase = sb + (uint32_t)(it & 1) * SM_ST;
        const int kc = it * 32;
        #pragma unroll
        for (int p = 0; p < 2; p++) {
            int idx = p * 256 + t;
            int r = idx >> 2, s4 = idx & 3;
            size_t so = (size_t)(m0 + r) * KPA + kc + s4 * 8;
            uint32_t doff = (uint32_t)(r * 80 + s4 * 16);
            cp16(sbase + SM_AH + doff, xhi + so);
            cp16(sbase + SM_AL + doff, xlo + so);
        }
        #pragma unroll
        for (int p = 0; p < 2; p++) {
            int idx = p * 256 + t;
            int r = idx >> 4, s8 = idx & 15;
            if (n0 + s8 * 8 < N) {
                size_t so = (size_t)(kc + r) * N + n0 + s8 * 8;
                uint32_t doff = (uint32_t)(r * 272 + s8 * 16);
                cp16(sbase + SM_BH + doff, whi + so);
                cp16(sbase + SM_BL + doff, wlo + so);
            }
        }
        cp_commit();
    };

    issue(0);
    for (int it = 0; it < KCH; it++) {
        cp_wait0();          // stage (it&1) data landed
        __syncthreads();     // visible to all; prior compute on other stage done
        if (it + 1 < KCH) issue(it + 1);   // overlaps compute below

        const uint32_t cb = sb + (uint32_t)(it & 1) * SM_ST;
        #pragma unroll
        for (int ks = 0; ks < 2; ks++) {
            uint32_t bh[8], bl[8];
            ldsm4t(bh,     cb + SM_BH + sbRel[0] + ks * 4352);
            ldsm4t(bh + 4, cb + SM_BH + sbRel[1] + ks * 4352);
            ldsm4t(bl,     cb + SM_BL + sbRel[0] + ks * 4352);
            ldsm4t(bl + 4, cb + SM_BL + sbRel[1] + ks * 4352);
            #pragma unroll
            for (int mi = 0; mi < 4; mi++) {
                uint32_t ah[4];
                ldsm4(ah, cb + SM_AH + saRel[mi] + ks * 32);
                mma16816(acc[mi][0], ah, bh + 0);
                mma16816(acc[mi][1], ah, bh + 2);
                mma16816(acc[mi][2], ah, bh + 4);
                mma16816(acc[mi][3], ah, bh + 6);
                mma16816(acc[mi][0], ah, bl + 0);
                mma16816(acc[mi][1], ah, bl + 2);
                mma16816(acc[mi][2], ah, bl + 4);
                mma16816(acc[mi][3], ah, bl + 6);
                uint32_t al[4];
                ldsm4(al, cb + SM_AL + saRel[mi] + ks * 32);
                mma16816(acc[mi][0], al, bh + 0);
                mma16816(acc[mi][1], al, bh + 2);
                mma16816(acc[mi][2], al, bh + 4);
                mma16816(acc[mi][3], al, bh + 6);
            }
        }
    }

    // epilogue: c-frag rows = lane>>2 (+8), cols = (lane&3)*2 (+1)
    #pragma unroll
    for (int mi = 0; mi < 4; mi++) {
        int r = m0 + wm + mi * 16 + (lane >> 2);
        #pragma unroll
        for (int nj = 0; nj < 4; nj++) {
            int c = n0 + wn + nj * 8 + (lane & 3) * 2;
            if (c < N) {
                #pragma unroll
                for (int half = 0; half < 2; half++) {
                    int rr = r + half * 8;
                    float v0 = acc[mi][nj][half * 2 + 0];
                    float v1 = acc[mi][nj][half * 2 + 1];
                    if (BIAS) { v0 += bias[c]; v1 += bias[c + 1]; }
                    if (SPLITOUT) {
                        v0 = gelu_f(v0); v1 = gelu_f(v1);
                        __align__(4) __nv_bfloat16 h2[2], l2[2];
                        h2[0] = __float2bfloat16(v0);
                        h2[1] = __float2bfloat16(v1);
                        l2[0] = __float2bfloat16(v0 - __bfloat162float(h2[0]));
                        l2[1] = __float2bfloat16(v1 - __bfloat162float(h2[1]));
                        *reinterpret_cast<uint32_t*>(&ohi[(size_t)rr * KP + c]) =
                            *reinterpret_cast<const uint32_t*>(h2);
                        *reinterpret_cast<uint32_t*>(&olo[(size_t)rr * KP + c]) =
                            *reinterpret_cast<const uint32_t*>(l2);
                    }
                    *reinterpret_cast<float2*>(&out[(size_t)rr * ldc + c]) =
                        make_float2(v0, v1);
                }
            }
        }
    }
}

// ---------------------------------------------------------------------------
// fp32 tiled GEMM (q only): 128x128x16, 8x8 microtiles, conflict-free.
// ---------------------------------------------------------------------------
template <bool GELU, bool BIAS>
__global__ void __launch_bounds__(256, 2)
k_gemm(const float* __restrict__ A, const int* __restrict__ gather, int lda,
       const float* __restrict__ Bm, int ldb, const float* __restrict__ bias,
       float* __restrict__ C, int ldc, int M, int N, int K) {
    __shared__ __align__(16) float sA[16][132];
    __shared__ __align__(16) float sB[16][128];
    const int t = threadIdx.x;
    const int n0 = blockIdx.x * 128, m0 = blockIdx.y * 128;
    const int rowA = t >> 1, kqA = (t & 1) * 8;
    const int kkB = t >> 4, nqB = (t & 15) * 4;
    const int tr4 = (t >> 4) * 4, tc4 = (t & 15) * 4;

    const int gm = m0 + rowA;
    const float* arow = nullptr;
    if (gm < M) arow = A + (size_t)(gather ? gather[gm] : gm) * lda;
    const bool bn0 = (n0 + nqB) < N;
    const bool bn1 = (n0 + 64 + nqB) < N;

    const float4 z4 = make_float4(0.f, 0.f, 0.f, 0.f);
    float4 aR0 = z4, aR1 = z4, bR0 = z4, bR1 = z4;
    {
        int ka = kqA;
        if (arow && ka < K) {
            aR0 = *reinterpret_cast<const float4*>(arow + ka);
            aR1 = *reinterpret_cast<const float4*>(arow + ka + 4);
        }
        int kb = kkB;
        if (kb < K) {
            const float* bp = Bm + (size_t)kb * ldb + n0 + nqB;
            if (bn0) bR0 = *reinterpret_cast<const float4*>(bp);
            if (bn1) bR1 = *reinterpret_cast<const float4*>(bp + 64);
        }
    }

    float acc[8][8] = {};
    for (int k0 = 0; k0 < K; k0 += 16) {
        __syncthreads();
        sA[kqA + 0][rowA] = aR0.x; sA[kqA + 1][rowA] = aR0.y;
        sA[kqA + 2][rowA] = aR0.z; sA[kqA + 3][rowA] = aR0.w;
        sA[kqA + 4][rowA] = aR1.x; sA[kqA + 5][rowA] = aR1.y;
        sA[kqA + 6][rowA] = aR1.z; sA[kqA + 7][rowA] = aR1.w;
        *reinterpret_cast<float4*>(&sB[kkB][nqB])      = bR0;
        *reinterpret_cast<float4*>(&sB[kkB][64 + nqB]) = bR1;

        int k1 = k0 + 16;
        if (k1 < K) {
            aR0 = z4; aR1 = z4; bR0 = z4; bR1 = z4;
            int ka = k1 + kqA;
            if (arow && ka < K) {
                aR0 = *reinterpret_cast<const float4*>(arow + ka);
                aR1 = *reinterpret_cast<const float4*>(arow + ka + 4);
            }
            int kb = k1 + kkB;
            if (kb < K) {
                const float* bp = Bm + (size_t)kb * ldb + n0 + nqB;
                if (bn0) bR0 = *reinterpret_cast<const float4*>(bp);
                if (bn1) bR1 = *reinterpret_cast<const float4*>(bp + 64);
            }
        }
        __syncthreads();

        #pragma unroll
        for (int kk = 0; kk < 16; kk++) {
            float4 a0 = *reinterpret_cast<const float4*>(&sA[kk][tr4]);
            float4 a1 = *reinterpret_cast<const float4*>(&sA[kk][64 + tr4]);
            float4 b0 = *reinterpret_cast<const float4*>(&sB[kk][tc4]);
            float4 b1 = *reinterpret_cast<const float4*>(&sB[kk][64 + tc4]);
            const float av[8] = {a0.x, a0.y, a0.z, a0.w, a1.x, a1.y, a1.z, a1.w};
            const float bv[8] = {b0.x, b0.y, b0.z, b0.w, b1.x, b1.y, b1.z, b1.w};
            #pragma unroll
            for (int i = 0; i < 8; i++)
                #pragma unroll
                for (int j = 0; j < 8; j++)
                    acc[i][j] += av[i] * bv[j];
        }
    }

    #pragma unroll
    for (int i = 0; i < 8; i++) {
        int m = m0 + ((i < 4) ? (tr4 + i) : (64 + tr4 + i - 4));
        if (m >= M) continue;
        #pragma unroll
        for (int jh = 0; jh < 2; jh++) {
            int n = n0 + jh * 64 + tc4;
            if (n >= N) continue;
            float4 v;
            v.x = acc[i][jh * 4 + 0]; v.y = acc[i][jh * 4 + 1];
            v.z = acc[i][jh * 4 + 2]; v.w = acc[i][jh * 4 + 3];
            if (BIAS) {
                v.x += bias[n + 0]; v.y += bias[n + 1];
                v.z += bias[n + 2]; v.w += bias[n + 3];
            }
            if (GELU) {
                v.x = gelu_f(v.x); v.y = gelu_f(v.y);
                v.z = gelu_f(v.z); v.w = gelu_f(v.w);
            }
            *reinterpret_cast<float4*>(&C[(size_t)m * ldc + n]) = v;
        }
    }
}

// ---------------------------------------------------------------------------
// Sparse aggregate + GELU, fused with bf16 hi/lo split for the next layer.
// ---------------------------------------------------------------------------
__global__ void k_sagg(const float* __restrict__ y, const uint8_t* __restrict__ nbr,
                       const int* __restrict__ cnt, float* __restrict__ xout,
                       __nv_bfloat16* __restrict__ hi, __nv_bfloat16* __restrict__ lo) {
    int bi = blockIdx.x;
    int b = bi / N_NODE, i = bi % N_NODE;
    int t = threadIdx.x;                 // 64
    __shared__ uint8_t sj[N_NODE];
    float4 acc = make_float4(0.f, 0.f, 0.f, 0.f);
    const float* yb = y + (size_t)b * N_NODE * RC;
    for (int r = 0; r < N_REL; r++) {
        int br = b * N_REL + r;
        int c = cnt[br * N_NODE + i];
        const uint8_t* base = nbr + ((size_t)br * N_NODE + i) * N_NODE;
        for (int s = t; s < c; s += 64) sj[s] = base[s];
        __syncthreads();
        if (t < 50) {
            const float* yr = yb + r * C_DIM + t * 4;
            float4 tmp = make_float4(0.f, 0.f, 0.f, 0.f);
            #pragma unroll 4
            for (int s = 0; s < c; s++) {
                float4 v = *reinterpret_cast<const float4*>(yr + (size_t)sj[s] * RC);
                tmp.x += v.x; tmp.y += v.y; tmp.z += v.z; tmp.w += v.w;
            }
            float inv = 1.0f / (float)c;
            acc.x += tmp.x * inv; acc.y += tmp.y * inv;
            acc.z += tmp.z * inv; acc.w += tmp.w * inv;
        }
        __syncthreads();
    }
    if (t < 50) {
        float o[4];
        o[0] = gelu_f(acc.x); o[1] = gelu_f(acc.y);
        o[2] = gelu_f(acc.z); o[3] = gelu_f(acc.w);
        *reinterpret_cast<float4*>(&xout[(size_t)bi * C_DIM + t * 4]) =
            make_float4(o[0], o[1], o[2], o[3]);
        __align__(8) __nv_bfloat16 h4[4], l4[4];
        #pragma unroll
        for (int j = 0; j < 4; j++) {
            __nv_bfloat16 h = __float2bfloat16(o[j]);
            h4[j] = h;
            l4[j] = __float2bfloat16(o[j] - __bfloat162float(h));
        }
        *reinterpret_cast<uint2*>(&hi[(size_t)bi * KP + t * 4]) = *reinterpret_cast<const uint2*>(h4);
        *reinterpret_cast<uint2*>(&lo[(size_t)bi * KP + t * 4]) = *reinterpret_cast<const uint2*>(l4);
    } else if (t < 56) {
        int col = C_DIM + (t - 50) * 4;   // 200..220, zero the K pad
        uint2 z = make_uint2(0, 0);
        *reinterpret_cast<uint2*>(&hi[(size_t)bi * KP + col]) = z;
        *reinterpret_cast<uint2*>(&lo[(size_t)bi * KP + col]) = z;
    }
}

// ---------------------------------------------------------------------------
// Attention pooling; k/v fused in one buffer with row stride 400 (k@0, v@200).
// ---------------------------------------------------------------------------
__global__ void k_attn(const float* __restrict__ q, const float* __restrict__ kv,
                       const int* __restrict__ lens,
                       float* __restrict__ out, float* __restrict__ gv) {
    int b = blockIdx.x;
    int t = threadIdx.x;   // 256
    __shared__ float sq[C_DIM];
    __shared__ float sa[2][N_NODE];
    __shared__ float red[256];
    if (t < C_DIM) sq[t] = q[b * C_DIM + t];
    __syncthreads();
    int len = lens[b];
    for (int h = 0; h < 2; h++) {
        float s = -INFINITY;
        if (t < N_NODE && t < len) {
            float acc = 0.f;
            const float* kr = kv + ((size_t)(b * N_NODE + t)) * 400 + h * 100;
            #pragma unroll 4
            for (int d = 0; d < 100; d++) acc += sq[h * 100 + d] * kr[d];
            s = acc * 0.1f;
        }
        red[t] = s;
        __syncthreads();
        for (int off = 128; off > 0; off >>= 1) {
            if (t < off) red[t] = fmaxf(red[t], red[t + off]);
            __syncthreads();
        }
        float mx = red[0];
        __syncthreads();
        float e = (t < N_NODE && t < len) ? expf(s - mx) : 0.f;
        red[t] = e;
        __syncthreads();
        for (int off = 128; off > 0; off >>= 1) {
            if (t < off) red[t] += red[t + off];
            __syncthreads();
        }
        float inv = 1.f / red[0];
        __syncthreads();
        if (t < N_NODE) {
            float a = e * inv;
            sa[h][t] = a;
            out[32 + ((size_t)(h * B_ + b)) * N_NODE + t] = a;
        }
        __syncthreads();
    }
    if (t < C_DIM) {
        int h = t / 100, d = t % 100;
        float g = 0.f;
        for (int l = 0; l < N_NODE; l++)
            g += sa[h][l] * kv[((size_t)(b * N_NODE + l)) * 400 + 200 + h * 100 + d];
        gv[b * C_DIM + t] = g;
    }
}

// ---------------------------------------------------------------------------
// MLP readout.
// ---------------------------------------------------------------------------
__global__ void k_mlp(const float* __restrict__ gv, const float* __restrict__ sent,
                      const float* __restrict__ W0, const float* __restrict__ b0,
                      const float* __restrict__ lng, const float* __restrict__ lnb,
                      const float* __restrict__ W1, const float* __restrict__ b1,
                      float* __restrict__ out) {
    int b = blockIdx.x;
    int t = threadIdx.x;   // 512
    const int ZD = C_DIM + SENT_DIM;
    __shared__ float zz[C_DIM + SENT_DIM];
    __shared__ float red[512];
    for (int i = t; i < ZD; i += 512)
        zz[i] = (i < C_DIM) ? gv[b * C_DIM + i] : sent[(size_t)b * SENT_DIM + (i - C_DIM)];
    __syncthreads();
    float acc = b0[t];
    #pragma unroll 4
    for (int k = 0; k < ZD; k++) acc += zz[k] * W0[(size_t)k * FC_DIM + t];
    red[t] = acc; __syncthreads();
    for (int off = 256; off > 0; off >>= 1) { if (t < off) red[t] += red[t + off]; __syncthreads(); }
    float mu = red[0] * (1.f / FC_DIM);
    __syncthreads();
    float d = acc - mu;
    red[t] = d * d; __syncthreads();
    for (int off = 256; off > 0; off >>= 1) { if (t < off) red[t] += red[t + off]; __syncthreads(); }
    float var = red[0] * (1.f / FC_DIM);
    __syncthreads();
    float h1 = gelu_f(d * rsqrtf(var + 1e-5f) * lng[t] + lnb[t]);
    red[t] = h1 * W1[t]; __syncthreads();
    for (int off = 256; off > 0; off >>= 1) { if (t < off) red[t] += red[t + off]; __syncthreads(); }
    if (t == 0) out[b] = red[0] + b1[0];
}

// ---------------------------------------------------------------------------
extern "C" void kernel_launch(void* const* d_in, const int* in_sizes, int n_in,
                              void* d_out, int out_size) {
    const float* sent     = (const float*)d_in[0];
    const int*   concepts = (const int*)  d_in[1];
    const float* adj      = (const float*)d_in[2];
    const int*   lens     = (const int*)  d_in[3];
    const float* emb      = (const float*)d_in[4];
    const float* cptW     = (const float*)d_in[5];
    const float* cptb     = (const float*)d_in[6];
    const float* gnnw     = (const float*)d_in[7];
    const float* wq       = (const float*)d_in[8];
    const float* bq       = (const float*)d_in[9];
    const float* wk       = (const float*)d_in[10];
    const float* bk       = (const float*)d_in[11];
    const float* wv       = (const float*)d_in[12];
    const float* bv       = (const float*)d_in[13];
    const float* fcW0     = (const float*)d_in[14];
    const float* fcb0     = (const float*)d_in[15];
    const float* lng      = (const float*)d_in[16];
    const float* lnb      = (const float*)d_in[17];
    const float* fcW1     = (const float*)d_in[18];
    const float* fcb1     = (const float*)d_in[19];
    float* out = (float*)d_out;

    float *px, *px2, *py, *pkv, *pq, *pgv, *pbkv;
    __nv_bfloat16 *pxhi, *pxlo, *pwhi, *pwlo, *pehi, *pelo, *pcwhi, *pcwlo, *pwkvhi, *pwkvlo;
    uint8_t* pnbr; int* pcnt;
    cudaGetSymbolAddress((void**)&px,    g_x);
    cudaGetSymbolAddress((void**)&px2,   g_x2);
    cudaGetSymbolAddress((void**)&py,    g_y);
    cudaGetSymbolAddress((void**)&pnbr,  g_nbr);
    cudaGetSymbolAddress((void**)&pcnt,  g_cnt);
    cudaGetSymbolAddress((void**)&pkv,   g_kv);
    cudaGetSymbolAddress((void**)&pq,    g_q);
    cudaGetSymbolAddress((void**)&pgv,   g_gv);
    cudaGetSymbolAddress((void**)&pxhi,  g_xhi);
    cudaGetSymbolAddress((void**)&pxlo,  g_xlo);
    cudaGetSymbolAddress((void**)&pwhi,  g_whi);
    cudaGetSymbolAddress((void**)&pwlo,  g_wlo);
    cudaGetSymbolAddress((void**)&pehi,  g_ehi);
    cudaGetSymbolAddress((void**)&pelo,  g_elo);
    cudaGetSymbolAddress((void**)&pcwhi, g_cwhi);
    cudaGetSymbolAddress((void**)&pcwlo, g_cwlo);
    cudaGetSymbolAddress((void**)&pwkvhi, g_wkvhi);
    cudaGetSymbolAddress((void**)&pwkvlo, g_wkvlo);
    cudaGetSymbolAddress((void**)&pbkv,  g_bkv);

    const int SMEM_MMA = 2 * 37888;   // 75776 bytes
    cudaFuncSetAttribute(k_mma<7, false, false>,
                         cudaFuncAttributeMaxDynamicSharedMemorySize, SMEM_MMA);
    cudaFuncSetAttribute(k_mma<32, true, true>,
                         cudaFuncAttributeMaxDynamicSharedMemorySize, SMEM_MMA);
    cudaFuncSetAttribute(k_mma<7, true, false>,
                         cudaFuncAttributeMaxDynamicSharedMemorySize, SMEM_MMA);

    // [0] merged elementwise prep
    k_msplit<<<27350, 256>>>(cptW, wk, wv, bk, bv, emb, concepts,
                             pcwhi, pcwlo, pwkvhi, pwkvlo, pbkv,
                             pehi, pelo, pxhi, pxlo);
    // [1] layer-weight prep
    k_wprep<<<3 * KP, 256>>>(gnnw, pwhi, pwlo);
    // [2] embedding mma (emits x + hi/lo)
    {
        dim3 g(2, ROWS / 128);
        k_mma<32, true, true><<<g, 256, SMEM_MMA>>>(pehi, pelo, pcwhi, pcwlo, cptb,
                                                    px, C_DIM, C_DIM, pxhi, pxlo);
    }
    // [3] layer 0 mma  <-- ncu capture lands here
    dim3 gMMA((RC + 127) / 128, ROWS / 128);   // 54 x 50
    k_mma<7, false, false><<<gMMA, 256, SMEM_MMA>>>(pxhi, pxlo, pwhi + (size_t)0 * WT_L,
                                                    pwlo + (size_t)0 * WT_L, nullptr, py, RC, RC,
                                                    nullptr, nullptr);
    // [4] sparse structure (needed before first sagg)
    k_build<<<NBR_, 256>>>(adj, pnbr, pcnt);
    // [5..] rest of the pipeline
    k_sagg<<<ROWS, 64>>>(py, pnbr, pcnt, px2, pxhi, pxlo);
    k_mma<7, false, false><<<gMMA, 256, SMEM_MMA>>>(pxhi, pxlo, pwhi + (size_t)1 * WT_L,
                                                    pwlo + (size_t)1 * WT_L, nullptr, py, RC, RC,
                                                    nullptr, nullptr);
    k_sagg<<<ROWS, 64>>>(py, pnbr, pcnt, px, pxhi, pxlo);
    k_mma<7, false, false><<<gMMA, 256, SMEM_MMA>>>(pxhi, pxlo, pwhi + (size_t)2 * WT_L,
                                                    pwlo + (size_t)2 * WT_L, nullptr, py, RC, RC,
                                                    nullptr, nullptr);
    k_sagg<<<ROWS, 64>>>(py, pnbr, pcnt, px2, pxhi, pxlo);   // final x in px2 + hi/lo

    // kv = x @ [wk|wv] + [bk|bv] on tensor path
    {
        dim3 g(4, ROWS / 128);
        k_mma<7, true, false><<<g, 256, SMEM_MMA>>>(pxhi, pxlo, pwkvhi, pwkvlo, pbkv,
                                                    pkv, 400, 400, nullptr, nullptr);
    }
    // q = sent @ wq + bq (fp32, tiny)
    {
        dim3 g(2, 1);
        k_gemm<false, true><<<g, 256>>>(sent, nullptr, SENT_DIM, wq, C_DIM, bq,
                                        pq, C_DIM, B_, C_DIM, SENT_DIM);
    }

    k_attn<<<B_, 256>>>(pq, pkv, lens, out, pgv);
    k_mlp<<<B_, 512>>>(pgv, sent, fcW0, fcb0, lng, lnb, fcW1, fcb1, out);
}